// round 2
// baseline (speedup 1.0000x reference)
#include <cuda_runtime.h>
#include <math.h>

// Problem constants
#define Bb   2
#define Lb   2048
#define Db   1024
#define Hb   16
#define DKb  64
#define Ub   40
#define BHb  32       // B*H
#define MRows 4096    // B*L

// Scratch (static device arrays; allocation APIs are forbidden)
__device__ float g_Q[Bb*Hb*Lb*DKb];   // [BH, L, DK]
__device__ float g_K[Bb*Hb*Lb*DKb];
__device__ float g_V[Bb*Hb*Lb*DKb];
__device__ float g_M[BHb*Lb];
__device__ int   g_top[BHb*Ub];

// ---------------------------------------------------------------------------
// Kernel 1: Y = X @ W^T + bias, stored in [B,H,L,DK] layout.
// X: [4096, 1024] row-major. W: [1024(out), 1024(in)] row-major.
// Tiled 128x128x16 fp32 GEMM, 256 threads, 8x8 per-thread microtile.
// ---------------------------------------------------------------------------
__global__ void __launch_bounds__(256) linear_kernel(
    const float* __restrict__ X, const float* __restrict__ W,
    const float* __restrict__ bias, int sel)
{
    __shared__ float As[16][132];   // [kk][m], padded
    __shared__ float Bs[16][132];   // [kk][n], padded

    float* Y = (sel == 0) ? g_Q : ((sel == 1) ? g_K : g_V);

    int tid = threadIdx.x;
    int m0 = blockIdx.y * 128;
    int n0 = blockIdx.x * 128;
    int tx = tid & 15;        // n direction
    int ty = tid >> 4;        // m direction

    float acc[8][8];
    #pragma unroll
    for (int i = 0; i < 8; i++)
        #pragma unroll
        for (int j = 0; j < 8; j++) acc[i][j] = 0.f;

    for (int k0 = 0; k0 < 1024; k0 += 16) {
        #pragma unroll
        for (int i = 0; i < 8; i++) {
            int lin = tid + i * 256;
            int kk = lin & 15;
            int r  = lin >> 4;
            As[kk][r] = X[(size_t)(m0 + r) * 1024 + k0 + kk];
            Bs[kk][r] = W[(size_t)(n0 + r) * 1024 + k0 + kk];
        }
        __syncthreads();

        #pragma unroll
        for (int kk = 0; kk < 16; kk++) {
            float4 a0 = *(const float4*)&As[kk][ty * 8];
            float4 a1 = *(const float4*)&As[kk][ty * 8 + 4];
            float4 b0 = *(const float4*)&Bs[kk][tx * 8];
            float4 b1 = *(const float4*)&Bs[kk][tx * 8 + 4];
            float a[8] = {a0.x,a0.y,a0.z,a0.w,a1.x,a1.y,a1.z,a1.w};
            float b[8] = {b0.x,b0.y,b0.z,b0.w,b1.x,b1.y,b1.z,b1.w};
            #pragma unroll
            for (int i = 0; i < 8; i++)
                #pragma unroll
                for (int j = 0; j < 8; j++)
                    acc[i][j] += a[i] * b[j];
        }
        __syncthreads();
    }

    // Store to [B,H,L,DK]
    #pragma unroll
    for (int i = 0; i < 8; i++) {
        int m  = m0 + ty * 8 + i;
        int bb = m >> 11;       // / L
        int l  = m & 2047;
        #pragma unroll
        for (int j = 0; j < 8; j++) {
            int n  = n0 + tx * 8 + j;
            int h  = n >> 6;
            int dk = n & 63;
            size_t off = (((size_t)(bb * Hb + h) * Lb) + l) * DKb + dk;
            Y[off] = acc[i][j] + bias[n];
        }
    }
}

// ---------------------------------------------------------------------------
// Kernel 2: M[bh,q] = max_k(Q.K) - mean_k(Q.K)  (no mask, full L)
// One block = (bh, 128 q rows). Q row in registers, K tiles in SMEM.
// ---------------------------------------------------------------------------
__global__ void __launch_bounds__(128) mscore_kernel()
{
    __shared__ float4 Ks[128][16];  // 32 KB
    int bh = blockIdx.y;
    int t  = threadIdx.x;
    int q  = blockIdx.x * 128 + t;

    float4 qr[16];
    const float4* Qp = (const float4*)(g_Q + ((size_t)bh * Lb + q) * DKb);
    #pragma unroll
    for (int j = 0; j < 16; j++) qr[j] = Qp[j];

    float mx = -INFINITY;
    float sm = 0.f;

    for (int kt = 0; kt < Lb; kt += 128) {
        __syncthreads();
        #pragma unroll
        for (int i = 0; i < 16; i++) {
            int lin = t + i * 128;
            int r = lin >> 4, c = lin & 15;
            Ks[r][c] = ((const float4*)(g_K + ((size_t)bh * Lb + kt + r) * DKb))[c];
        }
        __syncthreads();

        #pragma unroll 2
        for (int k = 0; k < 128; k++) {
            float s0 = 0.f, s1 = 0.f, s2 = 0.f, s3 = 0.f;
            #pragma unroll
            for (int j = 0; j < 16; j++) {
                float4 kv = Ks[k][j];
                float4 qv = qr[j];
                s0 += qv.x * kv.x;
                s1 += qv.y * kv.y;
                s2 += qv.z * kv.z;
                s3 += qv.w * kv.w;
            }
            float s = (s0 + s1) + (s2 + s3);
            mx = fmaxf(mx, s);
            sm += s;
        }
    }
    g_M[bh * Lb + q] = mx - sm * (1.f / (float)Lb);
}

// ---------------------------------------------------------------------------
// Kernel 3: top-40 of M per (b,h). Matches jax.lax.top_k ordering:
// descending values, ties -> lowest index (iterative argmax, stable).
// ---------------------------------------------------------------------------
__global__ void __launch_bounds__(256) topk_kernel()
{
    __shared__ float v[Lb];
    __shared__ float rv[256];
    __shared__ int   ri[256];

    int bh = blockIdx.x;
    int t  = threadIdx.x;

    for (int i = t; i < Lb; i += 256) v[i] = g_M[bh * Lb + i];
    __syncthreads();

    for (int u = 0; u < Ub; u++) {
        float bvv = -INFINITY;
        int   bii = 1 << 30;
        for (int i = t; i < Lb; i += 256) {
            float x = v[i];
            if (x > bvv) { bvv = x; bii = i; }
        }
        rv[t] = bvv; ri[t] = bii;
        __syncthreads();
        for (int s = 128; s > 0; s >>= 1) {
            if (t < s) {
                if (rv[t + s] > rv[t] ||
                    (rv[t + s] == rv[t] && ri[t + s] < ri[t])) {
                    rv[t] = rv[t + s]; ri[t] = ri[t + s];
                }
            }
            __syncthreads();
        }
        if (t == 0) {
            g_top[bh * Ub + u] = ri[0];
            v[ri[0]] = -INFINITY;
        }
        __syncthreads();
    }
}

// ---------------------------------------------------------------------------
// Kernel 4: sparse attention for the selected rows.
// One block = (bh, u). Scores + causal mask + softmax + P@V.
// out layout: [attn (B,U,D)] then [attn_probs (B,H,U,L)]
// ---------------------------------------------------------------------------
__global__ void __launch_bounds__(128) attn_kernel(float* __restrict__ out)
{
    __shared__ float s[Lb];
    __shared__ float qs[DKb];
    __shared__ float redA[4];
    __shared__ float redB[4];
    __shared__ float accs[128];

    int u  = blockIdx.x;
    int bh = blockIdx.y;
    int b  = bh >> 4;
    int h  = bh & 15;
    int t = threadIdx.x, lane = t & 31, w = t >> 5;

    int q = g_top[bh * Ub + u];
    if (t < DKb) qs[t] = g_Q[((size_t)bh * Lb + q) * DKb + t];
    __syncthreads();

    float2 qv = *(const float2*)&qs[lane * 2];

    // scores: each warp handles k = w, w+4, ...; lanes split DK, shfl-reduce
    for (int k = w; k < Lb; k += 4) {
        const float2 kv =
            *(const float2*)(g_K + ((size_t)bh * Lb + k) * DKb + lane * 2);
        float p = qv.x * kv.x + qv.y * kv.y;
        #pragma unroll
        for (int o = 16; o; o >>= 1) p += __shfl_xor_sync(0xffffffffu, p, o);
        if (lane == 0)
            s[k] = p * 0.125f + ((k > q) ? -1e9f : 0.f);
    }
    __syncthreads();

    // softmax
    float lm = -INFINITY;
    for (int k = t; k < Lb; k += 128) lm = fmaxf(lm, s[k]);
    #pragma unroll
    for (int o = 16; o; o >>= 1)
        lm = fmaxf(lm, __shfl_xor_sync(0xffffffffu, lm, o));
    if (lane == 0) redA[w] = lm;
    __syncthreads();
    float mv = fmaxf(fmaxf(redA[0], redA[1]), fmaxf(redA[2], redA[3]));

    float ls = 0.f;
    for (int k = t; k < Lb; k += 128) {
        float e = __expf(s[k] - mv);
        s[k] = e;
        ls += e;
    }
    #pragma unroll
    for (int o = 16; o; o >>= 1) ls += __shfl_xor_sync(0xffffffffu, ls, o);
    if (lane == 0) redB[w] = ls;
    __syncthreads();
    float inv = 1.f / (redB[0] + redB[1] + redB[2] + redB[3]);

    // write probs
    float* probs = out + (size_t)Bb * Ub * Db;
    size_t po = ((size_t)(bh * Ub + u)) * Lb;
    for (int k = t; k < Lb; k += 128) probs[po + k] = s[k] * inv;

    // attn = P @ V : thread (half, dk) accumulates half the k range
    int dk = t & 63, half = t >> 6;
    const float* Vp = g_V + (size_t)bh * Lb * DKb + dk;
    int kbase = half * (Lb / 2);
    float a0 = 0.f, a1 = 0.f, a2 = 0.f, a3 = 0.f;
    for (int k = kbase; k < kbase + Lb / 2; k += 4) {
        a0 += s[k]     * Vp[(size_t)(k)     * DKb];
        a1 += s[k + 1] * Vp[(size_t)(k + 1) * DKb];
        a2 += s[k + 2] * Vp[(size_t)(k + 2) * DKb];
        a3 += s[k + 3] * Vp[(size_t)(k + 3) * DKb];
    }
    accs[t] = (a0 + a1) + (a2 + a3);
    __syncthreads();
    if (t < 64)
        out[((size_t)(b * Ub + u)) * Db + h * DKb + t] =
            (accs[t] + accs[t + 64]) * inv;
}

// ---------------------------------------------------------------------------
extern "C" void kernel_launch(void* const* d_in, const int* in_sizes, int n_in,
                              void* d_out, int out_size)
{
    const float* query = (const float*)d_in[0];
    const float* key   = (const float*)d_in[1];
    const float* value = (const float*)d_in[2];
    const float* Wq    = (const float*)d_in[3];
    const float* bq    = (const float*)d_in[4];
    const float* Wk    = (const float*)d_in[5];
    const float* bk    = (const float*)d_in[6];
    const float* Wv    = (const float*)d_in[7];
    const float* bv    = (const float*)d_in[8];
    float* out = (float*)d_out;

    dim3 gg(8, 32);   // N/128, M/128
    linear_kernel<<<gg, 256>>>(query, Wq, bq, 0);
    linear_kernel<<<gg, 256>>>(key,   Wk, bk, 1);
    linear_kernel<<<gg, 256>>>(value, Wv, bv, 2);

    mscore_kernel<<<dim3(Lb / 128, BHb), 128>>>();
    topk_kernel<<<BHb, 256>>>();
    attn_kernel<<<dim3(Ub, BHb), 128>>>(out);
}

// round 11
// speedup vs baseline: 1.2509x; 1.2509x over previous
#include <cuda_runtime.h>
#include <math.h>
#include <stdint.h>

// Problem constants
#define Bb   2
#define Lb   2048
#define Db   1024
#define Hb   16
#define DKb  64
#define Ub   40
#define BHb  32
#define CAND 64          // refinement candidate count
#define RSPL 16          // key splits for refine kernel (keys/split = 128)

// Scratch (static device arrays; allocation APIs are forbidden)
__device__ float g_Q[Bb*Hb*Lb*DKb];   // [BH, L, DK]
__device__ float g_K[Bb*Hb*Lb*DKb];
__device__ float g_V[Bb*Hb*Lb*DKb];
__device__ float g_M[BHb*Lb];
__device__ int   g_cand[BHb*CAND];
__device__ float g_pM[BHb*RSPL*CAND];
__device__ float g_pS[BHb*RSPL*CAND];
__device__ int   g_top[BHb*Ub];

// ---------------------------------------------------------------------------
// Kernel 1a (Q,K): fp32 SIMT GEMM, bit-identical accumulation order to the
// round-2 passing kernel. Y = X @ W^T + bias -> [B,H,L,DK].
// ---------------------------------------------------------------------------
__global__ void __launch_bounds__(256) linear_fp32_kernel(
    const float* __restrict__ X, const float* __restrict__ W,
    const float* __restrict__ bias, int sel)
{
    __shared__ float As[16][132];   // [kk][m], padded
    __shared__ float Bs[16][132];   // [kk][n], padded

    float* Y = (sel == 0) ? g_Q : (sel == 1) ? g_K : g_V;

    int tid = threadIdx.x;
    int m0 = blockIdx.y * 128;
    int n0 = blockIdx.x * 128;
    int tx = tid & 15;        // n direction
    int ty = tid >> 4;        // m direction

    float acc[8][8];
    #pragma unroll
    for (int i = 0; i < 8; i++)
        #pragma unroll
        for (int j = 0; j < 8; j++) acc[i][j] = 0.f;

    for (int k0 = 0; k0 < 1024; k0 += 16) {
        #pragma unroll
        for (int i = 0; i < 8; i++) {
            int lin = tid + i * 256;
            int kk = lin & 15;
            int r  = lin >> 4;
            As[kk][r] = X[(size_t)(m0 + r) * 1024 + k0 + kk];
            Bs[kk][r] = W[(size_t)(n0 + r) * 1024 + k0 + kk];
        }
        __syncthreads();

        #pragma unroll
        for (int kk = 0; kk < 16; kk++) {
            float4 a0 = *(const float4*)&As[kk][ty * 8];
            float4 a1 = *(const float4*)&As[kk][ty * 8 + 4];
            float4 b0 = *(const float4*)&Bs[kk][tx * 8];
            float4 b1 = *(const float4*)&Bs[kk][tx * 8 + 4];
            float a[8] = {a0.x,a0.y,a0.z,a0.w,a1.x,a1.y,a1.z,a1.w};
            float b[8] = {b0.x,b0.y,b0.z,b0.w,b1.x,b1.y,b1.z,b1.w};
            #pragma unroll
            for (int i = 0; i < 8; i++)
                #pragma unroll
                for (int j = 0; j < 8; j++)
                    acc[i][j] += a[i] * b[j];
        }
        __syncthreads();
    }

    #pragma unroll
    for (int i = 0; i < 8; i++) {
        int m  = m0 + ty * 8 + i;
        int bb = m >> 11;
        int l  = m & 2047;
        #pragma unroll
        for (int j = 0; j < 8; j++) {
            int n  = n0 + tx * 8 + j;
            int h  = n >> 6;
            int dk = n & 63;
            size_t off = (((size_t)(bb * Hb + h) * Lb) + l) * DKb + dk;
            Y[off] = acc[i][j] + bias[n];
        }
    }
}

// ---------------------------------------------------------------------------
// tf32 helpers: split (hi + lo), mma.sync m16n8k8 TN
// PTX fragment mapping for m16n8k8 tf32 (gr = lane>>2, gc = lane&3):
//   A: a0=(gr,gc) a1=(gr+8,gc) a2=(gr,gc+4) a3=(gr+8,gc+4)
//   B: b0=(k=gc,n=gr) b1=(k=gc+4,n=gr)
//   C: c0=(gr,2gc) c1=(gr,2gc+1) c2=(gr+8,2gc) c3=(gr+8,2gc+1)
// ---------------------------------------------------------------------------
__device__ __forceinline__ uint32_t tf32_of(float v) {
    uint32_t r;
    asm("cvt.rna.tf32.f32 %0, %1;" : "=r"(r) : "f"(v));
    return r;
}
__device__ __forceinline__ void split_tf32(float v, uint32_t& hi, uint32_t& lo) {
    hi = tf32_of(v);
    lo = tf32_of(v - __uint_as_float(hi));
}
__device__ __forceinline__ void mma8(float* c,
                                     uint32_t a0, uint32_t a1, uint32_t a2, uint32_t a3,
                                     uint32_t b0, uint32_t b1) {
    asm volatile(
        "mma.sync.aligned.m16n8k8.row.col.f32.tf32.tf32.f32 "
        "{%0,%1,%2,%3}, {%4,%5,%6,%7}, {%8,%9}, {%0,%1,%2,%3};\n"
        : "+f"(c[0]), "+f"(c[1]), "+f"(c[2]), "+f"(c[3])
        : "r"(a0), "r"(a1), "r"(a2), "r"(a3), "r"(b0), "r"(b1));
}

// ---------------------------------------------------------------------------
// Kernel 1b (V): 3xTF32 split mma GEMM. V only needs ~1e-3 accuracy.
// ---------------------------------------------------------------------------
__global__ void __launch_bounds__(256) linear_tf32_kernel(
    const float* __restrict__ X, const float* __restrict__ W,
    const float* __restrict__ bias)
{
    __shared__ float Xs[128][36];
    __shared__ float Ws[128][36];
    float* Y = g_V;

    int tid  = threadIdx.x;
    int lane = tid & 31, warp = tid >> 5;
    int wm = warp >> 1, wn = warp & 1;
    int gr = lane >> 2, gc = lane & 3;
    int m0 = blockIdx.y * 128, n0 = blockIdx.x * 128;

    float acc[2][8][4];
    #pragma unroll
    for (int mt = 0; mt < 2; mt++)
        #pragma unroll
        for (int nt = 0; nt < 8; nt++)
            #pragma unroll
            for (int r = 0; r < 4; r++) acc[mt][nt][r] = 0.f;

    int lr = tid >> 3, lc = (tid & 7) * 4;

    for (int k0 = 0; k0 < Db; k0 += 32) {
        __syncthreads();
        #pragma unroll
        for (int i = 0; i < 4; i++) {
            int r = lr + i * 32;
            *(float4*)&Xs[r][lc] = *(const float4*)&X[(size_t)(m0 + r) * Db + k0 + lc];
            *(float4*)&Ws[r][lc] = *(const float4*)&W[(size_t)(n0 + r) * Db + k0 + lc];
        }
        __syncthreads();

        #pragma unroll
        for (int k8 = 0; k8 < 32; k8 += 8) {
            uint32_t ah[2][4], al[2][4];
            #pragma unroll
            for (int mt = 0; mt < 2; mt++) {
                int rb = wm * 32 + mt * 16;
                split_tf32(Xs[rb + gr][k8 + gc],         ah[mt][0], al[mt][0]);
                split_tf32(Xs[rb + gr + 8][k8 + gc],     ah[mt][1], al[mt][1]);
                split_tf32(Xs[rb + gr][k8 + gc + 4],     ah[mt][2], al[mt][2]);
                split_tf32(Xs[rb + gr + 8][k8 + gc + 4], ah[mt][3], al[mt][3]);
            }
            #pragma unroll
            for (int nt = 0; nt < 8; nt++) {
                int nb = wn * 64 + nt * 8;
                uint32_t bh0, bl0, bh1, bl1;
                split_tf32(Ws[nb + gr][k8 + gc],     bh0, bl0);
                split_tf32(Ws[nb + gr][k8 + gc + 4], bh1, bl1);
                #pragma unroll
                for (int mt = 0; mt < 2; mt++) {
                    mma8(acc[mt][nt], ah[mt][0], ah[mt][1], ah[mt][2], ah[mt][3], bh0, bh1);
                    mma8(acc[mt][nt], ah[mt][0], ah[mt][1], ah[mt][2], ah[mt][3], bl0, bl1);
                    mma8(acc[mt][nt], al[mt][0], al[mt][1], al[mt][2], al[mt][3], bh0, bh1);
                }
            }
        }
    }

    #pragma unroll
    for (int mt = 0; mt < 2; mt++) {
        int m_lo = m0 + wm * 32 + mt * 16 + gr;
        #pragma unroll
        for (int nt = 0; nt < 8; nt++) {
            int n = n0 + wn * 64 + nt * 8 + 2 * gc;
            float2 bv = *(const float2*)&bias[n];
            int h = n >> 6, dk = n & 63;
            {
                int m = m_lo, b = m >> 11, l = m & 2047;
                float2 o; o.x = acc[mt][nt][0] + bv.x; o.y = acc[mt][nt][1] + bv.y;
                *(float2*)&Y[(((size_t)(b * Hb + h) * Lb) + l) * DKb + dk] = o;
            }
            {
                int m = m_lo + 8, b = m >> 11, l = m & 2047;
                float2 o; o.x = acc[mt][nt][2] + bv.x; o.y = acc[mt][nt][3] + bv.y;
                *(float2*)&Y[(((size_t)(b * Hb + h) * Lb) + l) * DKb + dk] = o;
            }
        }
    }
}

// ---------------------------------------------------------------------------
// Kernel 2: approx M[bh,q] = max_k(Q.K) - mean_k(Q.K), split-tf32 3-term.
// Nominates candidates only; exact fp32 refine decides the final order.
// ---------------------------------------------------------------------------
__global__ void __launch_bounds__(256) mscore_tf32_kernel()
{
    extern __shared__ float smdyn[];
    float (*Qs)[68] = (float (*)[68])smdyn;
    float (*Ks)[68] = (float (*)[68])(smdyn + 128 * 68);
    float* rM = smdyn + 2 * 128 * 68;   // [2][128]
    float* rS = rM + 2 * 128;           // [2][128]

    int bh = blockIdx.y;
    int q0 = blockIdx.x * 128;
    int tid  = threadIdx.x;
    int lane = tid & 31, warp = tid >> 5;
    int wm = warp >> 1, wn = warp & 1;
    int gr = lane >> 2, gc = lane & 3;

    const float* Qg = g_Q + (size_t)bh * Lb * DKb;
    const float* Kg = g_K + (size_t)bh * Lb * DKb;

    int lr = tid >> 4, lc = (tid & 15) * 4;
    #pragma unroll
    for (int i = 0; i < 8; i++) {
        int r = lr + i * 16;
        *(float4*)&Qs[r][lc] = *(const float4*)&Qg[(size_t)(q0 + r) * DKb + lc];
    }

    float rmax[2][2], rsum[2][2];
    #pragma unroll
    for (int a = 0; a < 2; a++)
        #pragma unroll
        for (int b = 0; b < 2; b++) { rmax[a][b] = -INFINITY; rsum[a][b] = 0.f; }

    float acc[2][8][4];
    #pragma unroll
    for (int mt = 0; mt < 2; mt++)
        #pragma unroll
        for (int nt = 0; nt < 8; nt++)
            #pragma unroll
            for (int r = 0; r < 4; r++) acc[mt][nt][r] = 0.f;

    for (int kt = 0; kt < Lb; kt += 128) {
        __syncthreads();
        #pragma unroll
        for (int i = 0; i < 8; i++) {
            int r = lr + i * 16;
            *(float4*)&Ks[r][lc] = *(const float4*)&Kg[(size_t)(kt + r) * DKb + lc];
        }
        __syncthreads();

        #pragma unroll
        for (int k8 = 0; k8 < 64; k8 += 8) {
            uint32_t ah[2][4], al[2][4];
            #pragma unroll
            for (int mt = 0; mt < 2; mt++) {
                int rb = wm * 32 + mt * 16;
                split_tf32(Qs[rb + gr][k8 + gc],         ah[mt][0], al[mt][0]);
                split_tf32(Qs[rb + gr + 8][k8 + gc],     ah[mt][1], al[mt][1]);
                split_tf32(Qs[rb + gr][k8 + gc + 4],     ah[mt][2], al[mt][2]);
                split_tf32(Qs[rb + gr + 8][k8 + gc + 4], ah[mt][3], al[mt][3]);
            }
            #pragma unroll
            for (int nt = 0; nt < 8; nt++) {
                int nb = wn * 64 + nt * 8;
                uint32_t bh0, bl0, bh1, bl1;
                split_tf32(Ks[nb + gr][k8 + gc],     bh0, bl0);
                split_tf32(Ks[nb + gr][k8 + gc + 4], bh1, bl1);
                #pragma unroll
                for (int mt = 0; mt < 2; mt++) {
                    mma8(acc[mt][nt], ah[mt][0], ah[mt][1], ah[mt][2], ah[mt][3], bh0, bh1);
                    mma8(acc[mt][nt], ah[mt][0], ah[mt][1], ah[mt][2], ah[mt][3], bl0, bl1);
                    mma8(acc[mt][nt], al[mt][0], al[mt][1], al[mt][2], al[mt][3], bh0, bh1);
                }
            }
        }

        #pragma unroll
        for (int mt = 0; mt < 2; mt++) {
            float mx0 = -INFINITY, mx1 = -INFINITY, s0 = 0.f, s1 = 0.f;
            #pragma unroll
            for (int nt = 0; nt < 8; nt++) {
                mx0 = fmaxf(mx0, fmaxf(acc[mt][nt][0], acc[mt][nt][1]));
                mx1 = fmaxf(mx1, fmaxf(acc[mt][nt][2], acc[mt][nt][3]));
                s0 += acc[mt][nt][0] + acc[mt][nt][1];
                s1 += acc[mt][nt][2] + acc[mt][nt][3];
                acc[mt][nt][0] = 0.f; acc[mt][nt][1] = 0.f;
                acc[mt][nt][2] = 0.f; acc[mt][nt][3] = 0.f;
            }
            rmax[mt][0] = fmaxf(rmax[mt][0], mx0);
            rmax[mt][1] = fmaxf(rmax[mt][1], mx1);
            rsum[mt][0] += s0;
            rsum[mt][1] += s1;
        }
    }

    #pragma unroll
    for (int mt = 0; mt < 2; mt++)
        #pragma unroll
        for (int hf = 0; hf < 2; hf++) {
            float m = rmax[mt][hf], s = rsum[mt][hf];
            #pragma unroll
            for (int o = 1; o < 4; o <<= 1) {
                m = fmaxf(m, __shfl_xor_sync(0xffffffffu, m, o));
                s += __shfl_xor_sync(0xffffffffu, s, o);
            }
            if (gc == 0) {
                int row = wm * 32 + mt * 16 + hf * 8 + gr;
                rM[wn * 128 + row] = m;
                rS[wn * 128 + row] = s;
            }
        }
    __syncthreads();
    if (tid < 128) {
        float m = fmaxf(rM[tid], rM[128 + tid]);
        float s = rS[tid] + rS[128 + tid];
        g_M[bh * Lb + q0 + tid] = m - s * (1.f / (float)Lb);
    }
}

// ---------------------------------------------------------------------------
// Kernel 3: top-CAND candidates of approx M per (b,h) (iterative argmax)
// ---------------------------------------------------------------------------
__global__ void __launch_bounds__(256) cand_topk_kernel()
{
    __shared__ float v[Lb];
    __shared__ float rv[256];
    __shared__ int   ri[256];

    int bh = blockIdx.x;
    int t  = threadIdx.x;

    for (int i = t; i < Lb; i += 256) v[i] = g_M[bh * Lb + i];
    __syncthreads();

    for (int u = 0; u < CAND; u++) {
        float bvv = -INFINITY;
        int   bii = 1 << 30;
        for (int i = t; i < Lb; i += 256) {
            float x = v[i];
            if (x > bvv) { bvv = x; bii = i; }
        }
        rv[t] = bvv; ri[t] = bii;
        __syncthreads();
        for (int s = 128; s > 0; s >>= 1) {
            if (t < s) {
                if (rv[t + s] > rv[t] ||
                    (rv[t + s] == rv[t] && ri[t + s] < ri[t])) {
                    rv[t] = rv[t + s]; ri[t] = ri[t + s];
                }
            }
            __syncthreads();
        }
        if (t == 0) {
            g_cand[bh * CAND + u] = ri[0];
            v[ri[0]] = -INFINITY;
        }
        __syncthreads();
    }
}

// ---------------------------------------------------------------------------
// Kernel 4: exact fp32 refinement of M for the candidates.
// Per-key dot product structure identical to the round-2-passing mscore
// (4 float4-lane partials, (p0+p1)+(p2+p3)); max is exact vs that kernel.
// ---------------------------------------------------------------------------
__global__ void __launch_bounds__(CAND) refine_kernel()
{
    __shared__ float4 Ks[128][16];
    int bh = blockIdx.y;
    int s0 = blockIdx.x * 128;
    int t  = threadIdx.x;

    int qi = g_cand[bh * CAND + t];
    const float4* Qp = (const float4*)(g_Q + ((size_t)bh * Lb + qi) * DKb);
    float4 qr[16];
    #pragma unroll
    for (int j = 0; j < 16; j++) qr[j] = Qp[j];

    const float4* Kg = (const float4*)(g_K + ((size_t)bh * Lb + s0) * DKb);
    #pragma unroll
    for (int i = 0; i < 32; i++) {
        int lin = t + i * CAND;
        int r = lin >> 4, c = lin & 15;
        Ks[r][c] = Kg[r * 16 + c];
    }
    __syncthreads();

    float mx = -INFINITY, sm = 0.f;
    for (int k = 0; k < 128; k++) {
        float p0 = 0.f, p1 = 0.f, p2 = 0.f, p3 = 0.f;
        #pragma unroll
        for (int j = 0; j < 16; j++) {
            float4 kv = Ks[k][j];
            float4 qv = qr[j];
            p0 += qv.x * kv.x;
            p1 += qv.y * kv.y;
            p2 += qv.z * kv.z;
            p3 += qv.w * kv.w;
        }
        float s = (p0 + p1) + (p2 + p3);
        mx = fmaxf(mx, s);
        sm += s;
    }
    g_pM[(bh * RSPL + blockIdx.x) * CAND + t] = mx;
    g_pS[(bh * RSPL + blockIdx.x) * CAND + t] = sm;
}

// ---------------------------------------------------------------------------
// Kernel 5: combine refine partials -> exact M, select final top-40
// (descending, ties -> lowest original index). grid BHb, block CAND.
// ---------------------------------------------------------------------------
__global__ void __launch_bounds__(CAND) finalsel_kernel()
{
    __shared__ float sv[CAND];
    __shared__ int   si[CAND];
    __shared__ float rv[CAND];
    __shared__ int   ri[CAND];

    int bh = blockIdx.x;
    int t  = threadIdx.x;

    float m = -INFINITY, s = 0.f;
    for (int sp = 0; sp < RSPL; sp++) {
        m = fmaxf(m, g_pM[(bh * RSPL + sp) * CAND + t]);
        s += g_pS[(bh * RSPL + sp) * CAND + t];
    }
    sv[t] = m - s * (1.f / (float)Lb);
    si[t] = g_cand[bh * CAND + t];
    __syncthreads();

    for (int u = 0; u < Ub; u++) {
        rv[t] = sv[t]; ri[t] = t;   // slot index for invalidation
        __syncthreads();
        for (int st = CAND / 2; st > 0; st >>= 1) {
            if (t < st) {
                float va = rv[t], vb = rv[t + st];
                int sa = ri[t], sb = ri[t + st];
                if (vb > va || (vb == va && si[sb] < si[sa])) {
                    rv[t] = vb; ri[t] = sb;
                }
            }
            __syncthreads();
        }
        if (t == 0) {
            g_top[bh * Ub + u] = si[ri[0]];
            sv[ri[0]] = -INFINITY;
        }
        __syncthreads();
    }
}

// ---------------------------------------------------------------------------
// Kernel 6: sparse attention for the selected rows (fp32)
// ---------------------------------------------------------------------------
__global__ void __launch_bounds__(128) attn_kernel(float* __restrict__ out)
{
    __shared__ float s[Lb];
    __shared__ float qs[DKb];
    __shared__ float redA[4];
    __shared__ float redB[4];
    __shared__ float accs[128];

    int u  = blockIdx.x;
    int bh = blockIdx.y;
    int b  = bh >> 4;
    int h  = bh & 15;
    int t = threadIdx.x, lane = t & 31, w = t >> 5;

    int q = g_top[bh * Ub + u];
    if (t < DKb) qs[t] = g_Q[((size_t)bh * Lb + q) * DKb + t];
    __syncthreads();

    float2 qv = *(const float2*)&qs[lane * 2];

    for (int k = w; k < Lb; k += 4) {
        const float2 kv =
            *(const float2*)(g_K + ((size_t)bh * Lb + k) * DKb + lane * 2);
        float p = qv.x * kv.x + qv.y * kv.y;
        #pragma unroll
        for (int o = 16; o; o >>= 1) p += __shfl_xor_sync(0xffffffffu, p, o);
        if (lane == 0)
            s[k] = p * 0.125f + ((k > q) ? -1e9f : 0.f);
    }
    __syncthreads();

    float lm = -INFINITY;
    for (int k = t; k < Lb; k += 128) lm = fmaxf(lm, s[k]);
    #pragma unroll
    for (int o = 16; o; o >>= 1)
        lm = fmaxf(lm, __shfl_xor_sync(0xffffffffu, lm, o));
    if (lane == 0) redA[w] = lm;
    __syncthreads();
    float mv = fmaxf(fmaxf(redA[0], redA[1]), fmaxf(redA[2], redA[3]));

    float ls = 0.f;
    for (int k = t; k < Lb; k += 128) {
        float e = __expf(s[k] - mv);
        s[k] = e;
        ls += e;
    }
    #pragma unroll
    for (int o = 16; o; o >>= 1) ls += __shfl_xor_sync(0xffffffffu, ls, o);
    if (lane == 0) redB[w] = ls;
    __syncthreads();
    float inv = 1.f / (redB[0] + redB[1] + redB[2] + redB[3]);

    float* probs = out + (size_t)Bb * Ub * Db;
    size_t po = ((size_t)(bh * Ub + u)) * Lb;
    for (int k = t; k < Lb; k += 128) probs[po + k] = s[k] * inv;

    int dk = t & 63, half = t >> 6;
    const float* Vp = g_V + (size_t)bh * Lb * DKb + dk;
    int kbase = half * (Lb / 2);
    float a0 = 0.f, a1 = 0.f, a2 = 0.f, a3 = 0.f;
    for (int k = kbase; k < kbase + Lb / 2; k += 4) {
        a0 += s[k]     * Vp[(size_t)(k)     * DKb];
        a1 += s[k + 1] * Vp[(size_t)(k + 1) * DKb];
        a2 += s[k + 2] * Vp[(size_t)(k + 2) * DKb];
        a3 += s[k + 3] * Vp[(size_t)(k + 3) * DKb];
    }
    accs[t] = (a0 + a1) + (a2 + a3);
    __syncthreads();
    if (t < 64)
        out[((size_t)(b * Ub + u)) * Db + h * DKb + t] =
            (accs[t] + accs[t + 64]) * inv;
}

// ---------------------------------------------------------------------------
extern "C" void kernel_launch(void* const* d_in, const int* in_sizes, int n_in,
                              void* d_out, int out_size)
{
    const float* query = (const float*)d_in[0];
    const float* key   = (const float*)d_in[1];
    const float* value = (const float*)d_in[2];
    const float* Wq    = (const float*)d_in[3];
    const float* bq    = (const float*)d_in[4];
    const float* Wk    = (const float*)d_in[5];
    const float* bk    = (const float*)d_in[6];
    const float* Wv    = (const float*)d_in[7];
    const float* bv    = (const float*)d_in[8];
    float* out = (float*)d_out;

    const int mscoreSmem = (2 * 128 * 68 + 4 * 128) * 4;  // 71680 B
    cudaFuncSetAttribute(mscore_tf32_kernel,
                         cudaFuncAttributeMaxDynamicSharedMemorySize, mscoreSmem);

    dim3 gl(8, 32);   // N/128, M/128
    linear_fp32_kernel<<<gl, 256>>>(query, Wq, bq, 0);  // Q: bit-exact R2 path
    linear_fp32_kernel<<<gl, 256>>>(key,   Wk, bk, 1);  // K: bit-exact R2 path
    linear_tf32_kernel<<<gl, 256>>>(value, Wv, bv);     // V: tf32 3-term

    mscore_tf32_kernel<<<dim3(Lb / 128, BHb), 256, mscoreSmem>>>();
    cand_topk_kernel<<<BHb, 256>>>();
    refine_kernel<<<dim3(RSPL, BHb), CAND>>>();
    finalsel_kernel<<<BHb, CAND>>>();
    attn_kernel<<<dim3(Ub, BHb), 128>>>(out);
}

// round 12
// speedup vs baseline: 1.4427x; 1.1533x over previous
#include <cuda_runtime.h>
#include <math.h>
#include <stdint.h>

// Problem constants
#define Bb   2
#define Lb   2048
#define Db   1024
#define Hb   16
#define DKb  64
#define Ub   40
#define BHb  32
#define CAND 64          // refinement candidate count
#define RSPL 16          // key splits for refine kernel (keys/split = 128)

// Scratch (static device arrays; allocation APIs are forbidden)
__device__ float g_Q[Bb*Hb*Lb*DKb];   // [BH, L, DK]
__device__ float g_K[Bb*Hb*Lb*DKb];
__device__ float g_V[Bb*Hb*Lb*DKb];
__device__ float g_M[BHb*Lb];
__device__ int   g_cand[BHb*CAND];
__device__ float g_pM[BHb*RSPL*CAND];
__device__ float g_pS[BHb*RSPL*CAND];
__device__ int   g_top[BHb*Ub];

// ---------------------------------------------------------------------------
// Kernel 1a (Q,K): fp32 SIMT GEMM, bit-identical accumulation order to the
// round-2 passing kernel. Y = X @ W^T + bias -> [B,H,L,DK].  (FROZEN)
// ---------------------------------------------------------------------------
__global__ void __launch_bounds__(256) linear_fp32_kernel(
    const float* __restrict__ X, const float* __restrict__ W,
    const float* __restrict__ bias, int sel)
{
    __shared__ float As[16][132];   // [kk][m], padded
    __shared__ float Bs[16][132];   // [kk][n], padded

    float* Y = (sel == 0) ? g_Q : (sel == 1) ? g_K : g_V;

    int tid = threadIdx.x;
    int m0 = blockIdx.y * 128;
    int n0 = blockIdx.x * 128;
    int tx = tid & 15;        // n direction
    int ty = tid >> 4;        // m direction

    float acc[8][8];
    #pragma unroll
    for (int i = 0; i < 8; i++)
        #pragma unroll
        for (int j = 0; j < 8; j++) acc[i][j] = 0.f;

    for (int k0 = 0; k0 < 1024; k0 += 16) {
        #pragma unroll
        for (int i = 0; i < 8; i++) {
            int lin = tid + i * 256;
            int kk = lin & 15;
            int r  = lin >> 4;
            As[kk][r] = X[(size_t)(m0 + r) * 1024 + k0 + kk];
            Bs[kk][r] = W[(size_t)(n0 + r) * 1024 + k0 + kk];
        }
        __syncthreads();

        #pragma unroll
        for (int kk = 0; kk < 16; kk++) {
            float4 a0 = *(const float4*)&As[kk][ty * 8];
            float4 a1 = *(const float4*)&As[kk][ty * 8 + 4];
            float4 b0 = *(const float4*)&Bs[kk][tx * 8];
            float4 b1 = *(const float4*)&Bs[kk][tx * 8 + 4];
            float a[8] = {a0.x,a0.y,a0.z,a0.w,a1.x,a1.y,a1.z,a1.w};
            float b[8] = {b0.x,b0.y,b0.z,b0.w,b1.x,b1.y,b1.z,b1.w};
            #pragma unroll
            for (int i = 0; i < 8; i++)
                #pragma unroll
                for (int j = 0; j < 8; j++)
                    acc[i][j] += a[i] * b[j];
        }
        __syncthreads();
    }

    #pragma unroll
    for (int i = 0; i < 8; i++) {
        int m  = m0 + ty * 8 + i;
        int bb = m >> 11;
        int l  = m & 2047;
        #pragma unroll
        for (int j = 0; j < 8; j++) {
            int n  = n0 + tx * 8 + j;
            int h  = n >> 6;
            int dk = n & 63;
            size_t off = (((size_t)(bb * Hb + h) * Lb) + l) * DKb + dk;
            Y[off] = acc[i][j] + bias[n];
        }
    }
}

// ---------------------------------------------------------------------------
// tf32 helpers. PTX fragment mapping for m16n8k8 tf32 (gr=lane>>2, gc=lane&3):
//   A: a0=(gr,gc) a1=(gr+8,gc) a2=(gr,gc+4) a3=(gr+8,gc+4)
//   B: b0=(k=gc,n=gr) b1=(k=gc+4,n=gr)
//   C: c0=(gr,2gc) c1=(gr,2gc+1) c2=(gr+8,2gc) c3=(gr+8,2gc+1)
// ---------------------------------------------------------------------------
__device__ __forceinline__ uint32_t tf32_of(float v) {
    uint32_t r;
    asm("cvt.rna.tf32.f32 %0, %1;" : "=r"(r) : "f"(v));
    return r;
}
__device__ __forceinline__ void split_tf32(float v, uint32_t& hi, uint32_t& lo) {
    hi = tf32_of(v);
    lo = tf32_of(v - __uint_as_float(hi));
}
__device__ __forceinline__ void mma8(float* c,
                                     uint32_t a0, uint32_t a1, uint32_t a2, uint32_t a3,
                                     uint32_t b0, uint32_t b1) {
    asm volatile(
        "mma.sync.aligned.m16n8k8.row.col.f32.tf32.tf32.f32 "
        "{%0,%1,%2,%3}, {%4,%5,%6,%7}, {%8,%9}, {%0,%1,%2,%3};\n"
        : "+f"(c[0]), "+f"(c[1]), "+f"(c[2]), "+f"(c[3])
        : "r"(a0), "r"(a1), "r"(a2), "r"(a3), "r"(b0), "r"(b1));
}

// ---------------------------------------------------------------------------
// Kernel 1b (V): 3xTF32 split mma GEMM. V only needs ~1e-3 accuracy. (FROZEN)
// ---------------------------------------------------------------------------
__global__ void __launch_bounds__(256) linear_tf32_kernel(
    const float* __restrict__ X, const float* __restrict__ W,
    const float* __restrict__ bias)
{
    __shared__ float Xs[128][36];
    __shared__ float Ws[128][36];
    float* Y = g_V;

    int tid  = threadIdx.x;
    int lane = tid & 31, warp = tid >> 5;
    int wm = warp >> 1, wn = warp & 1;
    int gr = lane >> 2, gc = lane & 3;
    int m0 = blockIdx.y * 128, n0 = blockIdx.x * 128;

    float acc[2][8][4];
    #pragma unroll
    for (int mt = 0; mt < 2; mt++)
        #pragma unroll
        for (int nt = 0; nt < 8; nt++)
            #pragma unroll
            for (int r = 0; r < 4; r++) acc[mt][nt][r] = 0.f;

    int lr = tid >> 3, lc = (tid & 7) * 4;

    for (int k0 = 0; k0 < Db; k0 += 32) {
        __syncthreads();
        #pragma unroll
        for (int i = 0; i < 4; i++) {
            int r = lr + i * 32;
            *(float4*)&Xs[r][lc] = *(const float4*)&X[(size_t)(m0 + r) * Db + k0 + lc];
            *(float4*)&Ws[r][lc] = *(const float4*)&W[(size_t)(n0 + r) * Db + k0 + lc];
        }
        __syncthreads();

        #pragma unroll
        for (int k8 = 0; k8 < 32; k8 += 8) {
            uint32_t ah[2][4], al[2][4];
            #pragma unroll
            for (int mt = 0; mt < 2; mt++) {
                int rb = wm * 32 + mt * 16;
                split_tf32(Xs[rb + gr][k8 + gc],         ah[mt][0], al[mt][0]);
                split_tf32(Xs[rb + gr + 8][k8 + gc],     ah[mt][1], al[mt][1]);
                split_tf32(Xs[rb + gr][k8 + gc + 4],     ah[mt][2], al[mt][2]);
                split_tf32(Xs[rb + gr + 8][k8 + gc + 4], ah[mt][3], al[mt][3]);
            }
            #pragma unroll
            for (int nt = 0; nt < 8; nt++) {
                int nb = wn * 64 + nt * 8;
                uint32_t bh0, bl0, bh1, bl1;
                split_tf32(Ws[nb + gr][k8 + gc],     bh0, bl0);
                split_tf32(Ws[nb + gr][k8 + gc + 4], bh1, bl1);
                #pragma unroll
                for (int mt = 0; mt < 2; mt++) {
                    mma8(acc[mt][nt], ah[mt][0], ah[mt][1], ah[mt][2], ah[mt][3], bh0, bh1);
                    mma8(acc[mt][nt], ah[mt][0], ah[mt][1], ah[mt][2], ah[mt][3], bl0, bl1);
                    mma8(acc[mt][nt], al[mt][0], al[mt][1], al[mt][2], al[mt][3], bh0, bh1);
                }
            }
        }
    }

    #pragma unroll
    for (int mt = 0; mt < 2; mt++) {
        int m_lo = m0 + wm * 32 + mt * 16 + gr;
        #pragma unroll
        for (int nt = 0; nt < 8; nt++) {
            int n = n0 + wn * 64 + nt * 8 + 2 * gc;
            float2 bv = *(const float2*)&bias[n];
            int h = n >> 6, dk = n & 63;
            {
                int m = m_lo, b = m >> 11, l = m & 2047;
                float2 o; o.x = acc[mt][nt][0] + bv.x; o.y = acc[mt][nt][1] + bv.y;
                *(float2*)&Y[(((size_t)(b * Hb + h) * Lb) + l) * DKb + dk] = o;
            }
            {
                int m = m_lo + 8, b = m >> 11, l = m & 2047;
                float2 o; o.x = acc[mt][nt][2] + bv.x; o.y = acc[mt][nt][3] + bv.y;
                *(float2*)&Y[(((size_t)(b * Hb + h) * Lb) + l) * DKb + dk] = o;
            }
        }
    }
}

// ---------------------------------------------------------------------------
// Kernel 2: approx M[bh,q] = max_k(Q.K) - mean_k(Q.K), SINGLE-pass tf32.
// Error ~1e-3 << rank-40..64 containment margin (~0.1+). Nominator only;
// exact fp32 refine decides the final order.
// ---------------------------------------------------------------------------
__global__ void __launch_bounds__(256) mscore_tf32_kernel()
{
    extern __shared__ float smdyn[];
    float (*Qs)[68] = (float (*)[68])smdyn;
    float (*Ks)[68] = (float (*)[68])(smdyn + 128 * 68);
    float* rM = smdyn + 2 * 128 * 68;   // [2][128]
    float* rS = rM + 2 * 128;           // [2][128]

    int bh = blockIdx.y;
    int q0 = blockIdx.x * 128;
    int tid  = threadIdx.x;
    int lane = tid & 31, warp = tid >> 5;
    int wm = warp >> 1, wn = warp & 1;
    int gr = lane >> 2, gc = lane & 3;

    const float* Qg = g_Q + (size_t)bh * Lb * DKb;
    const float* Kg = g_K + (size_t)bh * Lb * DKb;

    int lr = tid >> 4, lc = (tid & 15) * 4;
    #pragma unroll
    for (int i = 0; i < 8; i++) {
        int r = lr + i * 16;
        *(float4*)&Qs[r][lc] = *(const float4*)&Qg[(size_t)(q0 + r) * DKb + lc];
    }

    float rmax[2][2], rsum[2][2];
    #pragma unroll
    for (int a = 0; a < 2; a++)
        #pragma unroll
        for (int b = 0; b < 2; b++) { rmax[a][b] = -INFINITY; rsum[a][b] = 0.f; }

    float acc[2][8][4];
    #pragma unroll
    for (int mt = 0; mt < 2; mt++)
        #pragma unroll
        for (int nt = 0; nt < 8; nt++)
            #pragma unroll
            for (int r = 0; r < 4; r++) acc[mt][nt][r] = 0.f;

    for (int kt = 0; kt < Lb; kt += 128) {
        __syncthreads();
        #pragma unroll
        for (int i = 0; i < 8; i++) {
            int r = lr + i * 16;
            *(float4*)&Ks[r][lc] = *(const float4*)&Kg[(size_t)(kt + r) * DKb + lc];
        }
        __syncthreads();

        #pragma unroll
        for (int k8 = 0; k8 < 64; k8 += 8) {
            uint32_t ah[2][4];
            #pragma unroll
            for (int mt = 0; mt < 2; mt++) {
                int rb = wm * 32 + mt * 16;
                ah[mt][0] = tf32_of(Qs[rb + gr][k8 + gc]);
                ah[mt][1] = tf32_of(Qs[rb + gr + 8][k8 + gc]);
                ah[mt][2] = tf32_of(Qs[rb + gr][k8 + gc + 4]);
                ah[mt][3] = tf32_of(Qs[rb + gr + 8][k8 + gc + 4]);
            }
            #pragma unroll
            for (int nt = 0; nt < 8; nt++) {
                int nb = wn * 64 + nt * 8;
                uint32_t bh0 = tf32_of(Ks[nb + gr][k8 + gc]);
                uint32_t bh1 = tf32_of(Ks[nb + gr][k8 + gc + 4]);
                #pragma unroll
                for (int mt = 0; mt < 2; mt++)
                    mma8(acc[mt][nt], ah[mt][0], ah[mt][1], ah[mt][2], ah[mt][3], bh0, bh1);
            }
        }

        #pragma unroll
        for (int mt = 0; mt < 2; mt++) {
            float mx0 = -INFINITY, mx1 = -INFINITY, s0 = 0.f, s1 = 0.f;
            #pragma unroll
            for (int nt = 0; nt < 8; nt++) {
                mx0 = fmaxf(mx0, fmaxf(acc[mt][nt][0], acc[mt][nt][1]));
                mx1 = fmaxf(mx1, fmaxf(acc[mt][nt][2], acc[mt][nt][3]));
                s0 += acc[mt][nt][0] + acc[mt][nt][1];
                s1 += acc[mt][nt][2] + acc[mt][nt][3];
                acc[mt][nt][0] = 0.f; acc[mt][nt][1] = 0.f;
                acc[mt][nt][2] = 0.f; acc[mt][nt][3] = 0.f;
            }
            rmax[mt][0] = fmaxf(rmax[mt][0], mx0);
            rmax[mt][1] = fmaxf(rmax[mt][1], mx1);
            rsum[mt][0] += s0;
            rsum[mt][1] += s1;
        }
    }

    #pragma unroll
    for (int mt = 0; mt < 2; mt++)
        #pragma unroll
        for (int hf = 0; hf < 2; hf++) {
            float m = rmax[mt][hf], s = rsum[mt][hf];
            #pragma unroll
            for (int o = 1; o < 4; o <<= 1) {
                m = fmaxf(m, __shfl_xor_sync(0xffffffffu, m, o));
                s += __shfl_xor_sync(0xffffffffu, s, o);
            }
            if (gc == 0) {
                int row = wm * 32 + mt * 16 + hf * 8 + gr;
                rM[wn * 128 + row] = m;
                rS[wn * 128 + row] = s;
            }
        }
    __syncthreads();
    if (tid < 128) {
        float m = fmaxf(rM[tid], rM[128 + tid]);
        float s = rS[tid] + rS[128 + tid];
        g_M[bh * Lb + q0 + tid] = m - s * (1.f / (float)Lb);
    }
}

// ---------------------------------------------------------------------------
// Kernel 3: top-CAND candidates of approx M per (b,h) (iterative argmax)
// ---------------------------------------------------------------------------
__global__ void __launch_bounds__(256) cand_topk_kernel()
{
    __shared__ float v[Lb];
    __shared__ float rv[256];
    __shared__ int   ri[256];

    int bh = blockIdx.x;
    int t  = threadIdx.x;

    for (int i = t; i < Lb; i += 256) v[i] = g_M[bh * Lb + i];
    __syncthreads();

    for (int u = 0; u < CAND; u++) {
        float bvv = -INFINITY;
        int   bii = 1 << 30;
        for (int i = t; i < Lb; i += 256) {
            float x = v[i];
            if (x > bvv) { bvv = x; bii = i; }
        }
        rv[t] = bvv; ri[t] = bii;
        __syncthreads();
        for (int s = 128; s > 0; s >>= 1) {
            if (t < s) {
                if (rv[t + s] > rv[t] ||
                    (rv[t + s] == rv[t] && ri[t + s] < ri[t])) {
                    rv[t] = rv[t + s]; ri[t] = ri[t + s];
                }
            }
            __syncthreads();
        }
        if (t == 0) {
            g_cand[bh * CAND + u] = ri[0];
            v[ri[0]] = -INFINITY;
        }
        __syncthreads();
    }
}

// ---------------------------------------------------------------------------
// Kernel 4: exact fp32 refinement of M for the candidates.  (FROZEN)
// ---------------------------------------------------------------------------
__global__ void __launch_bounds__(CAND) refine_kernel()
{
    __shared__ float4 Ks[128][16];
    int bh = blockIdx.y;
    int s0 = blockIdx.x * 128;
    int t  = threadIdx.x;

    int qi = g_cand[bh * CAND + t];
    const float4* Qp = (const float4*)(g_Q + ((size_t)bh * Lb + qi) * DKb);
    float4 qr[16];
    #pragma unroll
    for (int j = 0; j < 16; j++) qr[j] = Qp[j];

    const float4* Kg = (const float4*)(g_K + ((size_t)bh * Lb + s0) * DKb);
    #pragma unroll
    for (int i = 0; i < 32; i++) {
        int lin = t + i * CAND;
        int r = lin >> 4, c = lin & 15;
        Ks[r][c] = Kg[r * 16 + c];
    }
    __syncthreads();

    float mx = -INFINITY, sm = 0.f;
    for (int k = 0; k < 128; k++) {
        float p0 = 0.f, p1 = 0.f, p2 = 0.f, p3 = 0.f;
        #pragma unroll
        for (int j = 0; j < 16; j++) {
            float4 kv = Ks[k][j];
            float4 qv = qr[j];
            p0 += qv.x * kv.x;
            p1 += qv.y * kv.y;
            p2 += qv.z * kv.z;
            p3 += qv.w * kv.w;
        }
        float s = (p0 + p1) + (p2 + p3);
        mx = fmaxf(mx, s);
        sm += s;
    }
    g_pM[(bh * RSPL + blockIdx.x) * CAND + t] = mx;
    g_pS[(bh * RSPL + blockIdx.x) * CAND + t] = sm;
}

// ---------------------------------------------------------------------------
// Kernel 5: combine refine partials -> exact M, final top-40.  (FROZEN)
// ---------------------------------------------------------------------------
__global__ void __launch_bounds__(CAND) finalsel_kernel()
{
    __shared__ float sv[CAND];
    __shared__ int   si[CAND];
    __shared__ float rv[CAND];
    __shared__ int   ri[CAND];

    int bh = blockIdx.x;
    int t  = threadIdx.x;

    float m = -INFINITY, s = 0.f;
    for (int sp = 0; sp < RSPL; sp++) {
        m = fmaxf(m, g_pM[(bh * RSPL + sp) * CAND + t]);
        s += g_pS[(bh * RSPL + sp) * CAND + t];
    }
    sv[t] = m - s * (1.f / (float)Lb);
    si[t] = g_cand[bh * CAND + t];
    __syncthreads();

    for (int u = 0; u < Ub; u++) {
        rv[t] = sv[t]; ri[t] = t;   // slot index for invalidation
        __syncthreads();
        for (int st = CAND / 2; st > 0; st >>= 1) {
            if (t < st) {
                float va = rv[t], vb = rv[t + st];
                int sa = ri[t], sb = ri[t + st];
                if (vb > va || (vb == va && si[sb] < si[sa])) {
                    rv[t] = vb; ri[t] = sb;
                }
            }
            __syncthreads();
        }
        if (t == 0) {
            g_top[bh * Ub + u] = si[ri[0]];
            sv[ri[0]] = -INFINITY;
        }
        __syncthreads();
    }
}

// ---------------------------------------------------------------------------
// Kernel 6: sparse attention for the selected rows (fp32)  (FROZEN)
// ---------------------------------------------------------------------------
__global__ void __launch_bounds__(128) attn_kernel(float* __restrict__ out)
{
    __shared__ float s[Lb];
    __shared__ float qs[DKb];
    __shared__ float redA[4];
    __shared__ float redB[4];
    __shared__ float accs[128];

    int u  = blockIdx.x;
    int bh = blockIdx.y;
    int b  = bh >> 4;
    int h  = bh & 15;
    int t = threadIdx.x, lane = t & 31, w = t >> 5;

    int q = g_top[bh * Ub + u];
    if (t < DKb) qs[t] = g_Q[((size_t)bh * Lb + q) * DKb + t];
    __syncthreads();

    float2 qv = *(const float2*)&qs[lane * 2];

    for (int k = w; k < Lb; k += 4) {
        const float2 kv =
            *(const float2*)(g_K + ((size_t)bh * Lb + k) * DKb + lane * 2);
        float p = qv.x * kv.x + qv.y * kv.y;
        #pragma unroll
        for (int o = 16; o; o >>= 1) p += __shfl_xor_sync(0xffffffffu, p, o);
        if (lane == 0)
            s[k] = p * 0.125f + ((k > q) ? -1e9f : 0.f);
    }
    __syncthreads();

    float lm = -INFINITY;
    for (int k = t; k < Lb; k += 128) lm = fmaxf(lm, s[k]);
    #pragma unroll
    for (int o = 16; o; o >>= 1)
        lm = fmaxf(lm, __shfl_xor_sync(0xffffffffu, lm, o));
    if (lane == 0) redA[w] = lm;
    __syncthreads();
    float mv = fmaxf(fmaxf(redA[0], redA[1]), fmaxf(redA[2], redA[3]));

    float ls = 0.f;
    for (int k = t; k < Lb; k += 128) {
        float e = __expf(s[k] - mv);
        s[k] = e;
        ls += e;
    }
    #pragma unroll
    for (int o = 16; o; o >>= 1) ls += __shfl_xor_sync(0xffffffffu, ls, o);
    if (lane == 0) redB[w] = ls;
    __syncthreads();
    float inv = 1.f / (redB[0] + redB[1] + redB[2] + redB[3]);

    float* probs = out + (size_t)Bb * Ub * Db;
    size_t po = ((size_t)(bh * Ub + u)) * Lb;
    for (int k = t; k < Lb; k += 128) probs[po + k] = s[k] * inv;

    int dk = t & 63, half = t >> 6;
    const float* Vp = g_V + (size_t)bh * Lb * DKb + dk;
    int kbase = half * (Lb / 2);
    float a0 = 0.f, a1 = 0.f, a2 = 0.f, a3 = 0.f;
    for (int k = kbase; k < kbase + Lb / 2; k += 4) {
        a0 += s[k]     * Vp[(size_t)(k)     * DKb];
        a1 += s[k + 1] * Vp[(size_t)(k + 1) * DKb];
        a2 += s[k + 2] * Vp[(size_t)(k + 2) * DKb];
        a3 += s[k + 3] * Vp[(size_t)(k + 3) * DKb];
    }
    accs[t] = (a0 + a1) + (a2 + a3);
    __syncthreads();
    if (t < 64)
        out[((size_t)(b * Ub + u)) * Db + h * DKb + t] =
            (accs[t] + accs[t + 64]) * inv;
}

// ---------------------------------------------------------------------------
extern "C" void kernel_launch(void* const* d_in, const int* in_sizes, int n_in,
                              void* d_out, int out_size)
{
    const float* query = (const float*)d_in[0];
    const float* key   = (const float*)d_in[1];
    const float* value = (const float*)d_in[2];
    const float* Wq    = (const float*)d_in[3];
    const float* bq    = (const float*)d_in[4];
    const float* Wk    = (const float*)d_in[5];
    const float* bk    = (const float*)d_in[6];
    const float* Wv    = (const float*)d_in[7];
    const float* bv    = (const float*)d_in[8];
    float* out = (float*)d_out;

    const int mscoreSmem = (2 * 128 * 68 + 4 * 128) * 4;  // 71680 B
    cudaFuncSetAttribute(mscore_tf32_kernel,
                         cudaFuncAttributeMaxDynamicSharedMemorySize, mscoreSmem);

    dim3 gl(8, 32);   // N/128, M/128
    linear_fp32_kernel<<<gl, 256>>>(query, Wq, bq, 0);  // Q: bit-exact R2 path
    linear_fp32_kernel<<<gl, 256>>>(key,   Wk, bk, 1);  // K: bit-exact R2 path
    linear_tf32_kernel<<<gl, 256>>>(value, Wv, bv);     // V: tf32 3-term

    mscore_tf32_kernel<<<dim3(Lb / 128, BHb), 256, mscoreSmem>>>();
    cand_topk_kernel<<<BHb, 256>>>();
    refine_kernel<<<dim3(RSPL, BHb), CAND>>>();
    finalsel_kernel<<<BHb, CAND>>>();
    attn_kernel<<<dim3(Ub, BHb), 128>>>(out);
}

// round 13
// speedup vs baseline: 1.6078x; 1.1144x over previous
#include <cuda_runtime.h>
#include <math.h>
#include <stdint.h>

// Problem constants
#define Bb   2
#define Lb   2048
#define Db   1024
#define Hb   16
#define DKb  64
#define Ub   40
#define BHb  32
#define CAND 64          // refinement candidate count
#define RSPL 16          // key splits for refine kernel (keys/split = 128)

// Scratch (static device arrays; allocation APIs are forbidden)
__device__ float g_Q[Bb*Hb*Lb*DKb];   // [BH, L, DK]
__device__ float g_K[Bb*Hb*Lb*DKb];
__device__ float g_V[Bb*Hb*Lb*DKb];
__device__ float g_M[BHb*Lb];
__device__ int   g_cand[BHb*CAND];
__device__ float g_pM[BHb*RSPL*CAND];
__device__ float g_pS[BHb*RSPL*CAND];
__device__ int   g_top[BHb*Ub];

// ---------------------------------------------------------------------------
// Kernel 1a (Q,K merged, gridDim.z selects): fp32 SIMT GEMM with register-
// staged double buffering. Per-output-element FFMA chain is k-ascending and
// IDENTICAL to the round-2/11/12 passing kernel -> g_Q/g_K bit-exact.
// ---------------------------------------------------------------------------
__global__ void __launch_bounds__(256, 2) linear_fp32_qk_kernel(
    const float* __restrict__ Xq, const float* __restrict__ Wq_, const float* __restrict__ bq_,
    const float* __restrict__ Xk, const float* __restrict__ Wk_, const float* __restrict__ bk_)
{
    __shared__ float As[2][16][132];   // [buf][kk][m]
    __shared__ float Bs[2][16][132];   // [buf][kk][n]

    const float *X, *W, *bias;
    float* Y;
    if (blockIdx.z == 0) { X = Xq; W = Wq_; bias = bq_; Y = g_Q; }
    else                 { X = Xk; W = Wk_; bias = bk_; Y = g_K; }

    int tid = threadIdx.x;
    int m0 = blockIdx.y * 128;
    int n0 = blockIdx.x * 128;
    int tx = tid & 15;        // n direction
    int ty = tid >> 4;        // m direction

    float acc[8][8];
    #pragma unroll
    for (int i = 0; i < 8; i++)
        #pragma unroll
        for (int j = 0; j < 8; j++) acc[i][j] = 0.f;

    float xr[8], wr[8];
    int kkq[8], rq[8];
    #pragma unroll
    for (int i = 0; i < 8; i++) {
        int lin = tid + i * 256;
        kkq[i] = lin & 15;
        rq[i]  = lin >> 4;
    }

    // prologue: tile 0 -> regs -> smem buf 0
    #pragma unroll
    for (int i = 0; i < 8; i++) {
        xr[i] = X[(size_t)(m0 + rq[i]) * 1024 + kkq[i]];
        wr[i] = W[(size_t)(n0 + rq[i]) * 1024 + kkq[i]];
    }
    #pragma unroll
    for (int i = 0; i < 8; i++) {
        As[0][kkq[i]][rq[i]] = xr[i];
        Bs[0][kkq[i]][rq[i]] = wr[i];
    }
    __syncthreads();

    for (int t = 0; t < 64; t++) {
        int buf = t & 1;
        if (t + 1 < 64) {
            int k0 = (t + 1) * 16;
            #pragma unroll
            for (int i = 0; i < 8; i++) {
                xr[i] = X[(size_t)(m0 + rq[i]) * 1024 + k0 + kkq[i]];
                wr[i] = W[(size_t)(n0 + rq[i]) * 1024 + k0 + kkq[i]];
            }
        }

        #pragma unroll
        for (int kk = 0; kk < 16; kk++) {
            float4 a0 = *(const float4*)&As[buf][kk][ty * 8];
            float4 a1 = *(const float4*)&As[buf][kk][ty * 8 + 4];
            float4 b0 = *(const float4*)&Bs[buf][kk][tx * 8];
            float4 b1 = *(const float4*)&Bs[buf][kk][tx * 8 + 4];
            float a[8] = {a0.x,a0.y,a0.z,a0.w,a1.x,a1.y,a1.z,a1.w};
            float b[8] = {b0.x,b0.y,b0.z,b0.w,b1.x,b1.y,b1.z,b1.w};
            #pragma unroll
            for (int i = 0; i < 8; i++)
                #pragma unroll
                for (int j = 0; j < 8; j++)
                    acc[i][j] += a[i] * b[j];
        }

        if (t + 1 < 64) {
            // buf^1 was last read in iteration t-1; all threads passed the
            // sync ending t-1, so overwriting it here is safe.
            #pragma unroll
            for (int i = 0; i < 8; i++) {
                As[buf ^ 1][kkq[i]][rq[i]] = xr[i];
                Bs[buf ^ 1][kkq[i]][rq[i]] = wr[i];
            }
        }
        __syncthreads();
    }

    #pragma unroll
    for (int i = 0; i < 8; i++) {
        int m  = m0 + ty * 8 + i;
        int bb = m >> 11;
        int l  = m & 2047;
        #pragma unroll
        for (int j = 0; j < 8; j++) {
            int n  = n0 + tx * 8 + j;
            int h  = n >> 6;
            int dk = n & 63;
            size_t off = (((size_t)(bb * Hb + h) * Lb) + l) * DKb + dk;
            Y[off] = acc[i][j] + bias[n];
        }
    }
}

// ---------------------------------------------------------------------------
// tf32 helpers. PTX fragment mapping for m16n8k8 tf32 (gr=lane>>2, gc=lane&3):
//   A: a0=(gr,gc) a1=(gr+8,gc) a2=(gr,gc+4) a3=(gr+8,gc+4)
//   B: b0=(k=gc,n=gr) b1=(k=gc+4,n=gr)
//   C: c0=(gr,2gc) c1=(gr,2gc+1) c2=(gr+8,2gc) c3=(gr+8,2gc+1)
// ---------------------------------------------------------------------------
__device__ __forceinline__ uint32_t tf32_of(float v) {
    uint32_t r;
    asm("cvt.rna.tf32.f32 %0, %1;" : "=r"(r) : "f"(v));
    return r;
}
__device__ __forceinline__ void split_tf32(float v, uint32_t& hi, uint32_t& lo) {
    hi = tf32_of(v);
    lo = tf32_of(v - __uint_as_float(hi));
}
__device__ __forceinline__ void mma8(float* c,
                                     uint32_t a0, uint32_t a1, uint32_t a2, uint32_t a3,
                                     uint32_t b0, uint32_t b1) {
    asm volatile(
        "mma.sync.aligned.m16n8k8.row.col.f32.tf32.tf32.f32 "
        "{%0,%1,%2,%3}, {%4,%5,%6,%7}, {%8,%9}, {%0,%1,%2,%3};\n"
        : "+f"(c[0]), "+f"(c[1]), "+f"(c[2]), "+f"(c[3])
        : "r"(a0), "r"(a1), "r"(a2), "r"(a3), "r"(b0), "r"(b1));
}

// ---------------------------------------------------------------------------
// Kernel 1b (V): 3xTF32 split mma GEMM. V only needs ~1e-3 accuracy. (FROZEN)
// ---------------------------------------------------------------------------
__global__ void __launch_bounds__(256) linear_tf32_kernel(
    const float* __restrict__ X, const float* __restrict__ W,
    const float* __restrict__ bias)
{
    __shared__ float Xs[128][36];
    __shared__ float Ws[128][36];
    float* Y = g_V;

    int tid  = threadIdx.x;
    int lane = tid & 31, warp = tid >> 5;
    int wm = warp >> 1, wn = warp & 1;
    int gr = lane >> 2, gc = lane & 3;
    int m0 = blockIdx.y * 128, n0 = blockIdx.x * 128;

    float acc[2][8][4];
    #pragma unroll
    for (int mt = 0; mt < 2; mt++)
        #pragma unroll
        for (int nt = 0; nt < 8; nt++)
            #pragma unroll
            for (int r = 0; r < 4; r++) acc[mt][nt][r] = 0.f;

    int lr = tid >> 3, lc = (tid & 7) * 4;

    for (int k0 = 0; k0 < Db; k0 += 32) {
        __syncthreads();
        #pragma unroll
        for (int i = 0; i < 4; i++) {
            int r = lr + i * 32;
            *(float4*)&Xs[r][lc] = *(const float4*)&X[(size_t)(m0 + r) * Db + k0 + lc];
            *(float4*)&Ws[r][lc] = *(const float4*)&W[(size_t)(n0 + r) * Db + k0 + lc];
        }
        __syncthreads();

        #pragma unroll
        for (int k8 = 0; k8 < 32; k8 += 8) {
            uint32_t ah[2][4], al[2][4];
            #pragma unroll
            for (int mt = 0; mt < 2; mt++) {
                int rb = wm * 32 + mt * 16;
                split_tf32(Xs[rb + gr][k8 + gc],         ah[mt][0], al[mt][0]);
                split_tf32(Xs[rb + gr + 8][k8 + gc],     ah[mt][1], al[mt][1]);
                split_tf32(Xs[rb + gr][k8 + gc + 4],     ah[mt][2], al[mt][2]);
                split_tf32(Xs[rb + gr + 8][k8 + gc + 4], ah[mt][3], al[mt][3]);
            }
            #pragma unroll
            for (int nt = 0; nt < 8; nt++) {
                int nb = wn * 64 + nt * 8;
                uint32_t bh0, bl0, bh1, bl1;
                split_tf32(Ws[nb + gr][k8 + gc],     bh0, bl0);
                split_tf32(Ws[nb + gr][k8 + gc + 4], bh1, bl1);
                #pragma unroll
                for (int mt = 0; mt < 2; mt++) {
                    mma8(acc[mt][nt], ah[mt][0], ah[mt][1], ah[mt][2], ah[mt][3], bh0, bh1);
                    mma8(acc[mt][nt], ah[mt][0], ah[mt][1], ah[mt][2], ah[mt][3], bl0, bl1);
                    mma8(acc[mt][nt], al[mt][0], al[mt][1], al[mt][2], al[mt][3], bh0, bh1);
                }
            }
        }
    }

    #pragma unroll
    for (int mt = 0; mt < 2; mt++) {
        int m_lo = m0 + wm * 32 + mt * 16 + gr;
        #pragma unroll
        for (int nt = 0; nt < 8; nt++) {
            int n = n0 + wn * 64 + nt * 8 + 2 * gc;
            float2 bv = *(const float2*)&bias[n];
            int h = n >> 6, dk = n & 63;
            {
                int m = m_lo, b = m >> 11, l = m & 2047;
                float2 o; o.x = acc[mt][nt][0] + bv.x; o.y = acc[mt][nt][1] + bv.y;
                *(float2*)&Y[(((size_t)(b * Hb + h) * Lb) + l) * DKb + dk] = o;
            }
            {
                int m = m_lo + 8, b = m >> 11, l = m & 2047;
                float2 o; o.x = acc[mt][nt][2] + bv.x; o.y = acc[mt][nt][3] + bv.y;
                *(float2*)&Y[(((size_t)(b * Hb + h) * Lb) + l) * DKb + dk] = o;
            }
        }
    }
}

// ---------------------------------------------------------------------------
// Kernel 2: approx M[bh,q] = max_k(Q.K) - mean_k(Q.K), single-pass tf32.
// tf32 conversion hoisted to tile-load time (SMEM holds converted bits) ->
// mainloop is pure LDS + HMMA; mma inputs bit-identical to the R12 kernel.
// ---------------------------------------------------------------------------
__global__ void __launch_bounds__(256) mscore_tf32_kernel()
{
    extern __shared__ float smdyn[];
    float (*Qs)[68] = (float (*)[68])smdyn;
    float (*Ks)[68] = (float (*)[68])(smdyn + 128 * 68);
    float* rM = smdyn + 2 * 128 * 68;   // [2][128]
    float* rS = rM + 2 * 128;           // [2][128]

    int bh = blockIdx.y;
    int q0 = blockIdx.x * 128;
    int tid  = threadIdx.x;
    int lane = tid & 31, warp = tid >> 5;
    int wm = warp >> 1, wn = warp & 1;
    int gr = lane >> 2, gc = lane & 3;

    const float* Qg = g_Q + (size_t)bh * Lb * DKb;
    const float* Kg = g_K + (size_t)bh * Lb * DKb;

    int lr = tid >> 4, lc = (tid & 15) * 4;
    #pragma unroll
    for (int i = 0; i < 8; i++) {
        int r = lr + i * 16;
        float4 v = *(const float4*)&Qg[(size_t)(q0 + r) * DKb + lc];
        v.x = __uint_as_float(tf32_of(v.x));
        v.y = __uint_as_float(tf32_of(v.y));
        v.z = __uint_as_float(tf32_of(v.z));
        v.w = __uint_as_float(tf32_of(v.w));
        *(float4*)&Qs[r][lc] = v;
    }

    float rmax[2][2], rsum[2][2];
    #pragma unroll
    for (int a = 0; a < 2; a++)
        #pragma unroll
        for (int b = 0; b < 2; b++) { rmax[a][b] = -INFINITY; rsum[a][b] = 0.f; }

    float acc[2][8][4];
    #pragma unroll
    for (int mt = 0; mt < 2; mt++)
        #pragma unroll
        for (int nt = 0; nt < 8; nt++)
            #pragma unroll
            for (int r = 0; r < 4; r++) acc[mt][nt][r] = 0.f;

    for (int kt = 0; kt < Lb; kt += 128) {
        __syncthreads();
        #pragma unroll
        for (int i = 0; i < 8; i++) {
            int r = lr + i * 16;
            float4 v = *(const float4*)&Kg[(size_t)(kt + r) * DKb + lc];
            v.x = __uint_as_float(tf32_of(v.x));
            v.y = __uint_as_float(tf32_of(v.y));
            v.z = __uint_as_float(tf32_of(v.z));
            v.w = __uint_as_float(tf32_of(v.w));
            *(float4*)&Ks[r][lc] = v;
        }
        __syncthreads();

        #pragma unroll
        for (int k8 = 0; k8 < 64; k8 += 8) {
            uint32_t ah[2][4];
            #pragma unroll
            for (int mt = 0; mt < 2; mt++) {
                int rb = wm * 32 + mt * 16;
                ah[mt][0] = __float_as_uint(Qs[rb + gr][k8 + gc]);
                ah[mt][1] = __float_as_uint(Qs[rb + gr + 8][k8 + gc]);
                ah[mt][2] = __float_as_uint(Qs[rb + gr][k8 + gc + 4]);
                ah[mt][3] = __float_as_uint(Qs[rb + gr + 8][k8 + gc + 4]);
            }
            #pragma unroll
            for (int nt = 0; nt < 8; nt++) {
                int nb = wn * 64 + nt * 8;
                uint32_t bh0 = __float_as_uint(Ks[nb + gr][k8 + gc]);
                uint32_t bh1 = __float_as_uint(Ks[nb + gr][k8 + gc + 4]);
                #pragma unroll
                for (int mt = 0; mt < 2; mt++)
                    mma8(acc[mt][nt], ah[mt][0], ah[mt][1], ah[mt][2], ah[mt][3], bh0, bh1);
            }
        }

        #pragma unroll
        for (int mt = 0; mt < 2; mt++) {
            float mx0 = -INFINITY, mx1 = -INFINITY, s0 = 0.f, s1 = 0.f;
            #pragma unroll
            for (int nt = 0; nt < 8; nt++) {
                mx0 = fmaxf(mx0, fmaxf(acc[mt][nt][0], acc[mt][nt][1]));
                mx1 = fmaxf(mx1, fmaxf(acc[mt][nt][2], acc[mt][nt][3]));
                s0 += acc[mt][nt][0] + acc[mt][nt][1];
                s1 += acc[mt][nt][2] + acc[mt][nt][3];
                acc[mt][nt][0] = 0.f; acc[mt][nt][1] = 0.f;
                acc[mt][nt][2] = 0.f; acc[mt][nt][3] = 0.f;
            }
            rmax[mt][0] = fmaxf(rmax[mt][0], mx0);
            rmax[mt][1] = fmaxf(rmax[mt][1], mx1);
            rsum[mt][0] += s0;
            rsum[mt][1] += s1;
        }
    }

    #pragma unroll
    for (int mt = 0; mt < 2; mt++)
        #pragma unroll
        for (int hf = 0; hf < 2; hf++) {
            float m = rmax[mt][hf], s = rsum[mt][hf];
            #pragma unroll
            for (int o = 1; o < 4; o <<= 1) {
                m = fmaxf(m, __shfl_xor_sync(0xffffffffu, m, o));
                s += __shfl_xor_sync(0xffffffffu, s, o);
            }
            if (gc == 0) {
                int row = wm * 32 + mt * 16 + hf * 8 + gr;
                rM[wn * 128 + row] = m;
                rS[wn * 128 + row] = s;
            }
        }
    __syncthreads();
    if (tid < 128) {
        float m = fmaxf(rM[tid], rM[128 + tid]);
        float s = rS[tid] + rS[128 + tid];
        g_M[bh * Lb + q0 + tid] = m - s * (1.f / (float)Lb);
    }
}

// ---------------------------------------------------------------------------
// Kernel 3: top-CAND candidates of approx M per (b,h) (iterative argmax)
// ---------------------------------------------------------------------------
__global__ void __launch_bounds__(256) cand_topk_kernel()
{
    __shared__ float v[Lb];
    __shared__ float rv[256];
    __shared__ int   ri[256];

    int bh = blockIdx.x;
    int t  = threadIdx.x;

    for (int i = t; i < Lb; i += 256) v[i] = g_M[bh * Lb + i];
    __syncthreads();

    for (int u = 0; u < CAND; u++) {
        float bvv = -INFINITY;
        int   bii = 1 << 30;
        for (int i = t; i < Lb; i += 256) {
            float x = v[i];
            if (x > bvv) { bvv = x; bii = i; }
        }
        rv[t] = bvv; ri[t] = bii;
        __syncthreads();
        for (int s = 128; s > 0; s >>= 1) {
            if (t < s) {
                if (rv[t + s] > rv[t] ||
                    (rv[t + s] == rv[t] && ri[t + s] < ri[t])) {
                    rv[t] = rv[t + s]; ri[t] = ri[t + s];
                }
            }
            __syncthreads();
        }
        if (t == 0) {
            g_cand[bh * CAND + u] = ri[0];
            v[ri[0]] = -INFINITY;
        }
        __syncthreads();
    }
}

// ---------------------------------------------------------------------------
// Kernel 4: exact fp32 refinement of M for the candidates.  (FROZEN)
// ---------------------------------------------------------------------------
__global__ void __launch_bounds__(CAND) refine_kernel()
{
    __shared__ float4 Ks[128][16];
    int bh = blockIdx.y;
    int s0 = blockIdx.x * 128;
    int t  = threadIdx.x;

    int qi = g_cand[bh * CAND + t];
    const float4* Qp = (const float4*)(g_Q + ((size_t)bh * Lb + qi) * DKb);
    float4 qr[16];
    #pragma unroll
    for (int j = 0; j < 16; j++) qr[j] = Qp[j];

    const float4* Kg = (const float4*)(g_K + ((size_t)bh * Lb + s0) * DKb);
    #pragma unroll
    for (int i = 0; i < 32; i++) {
        int lin = t + i * CAND;
        int r = lin >> 4, c = lin & 15;
        Ks[r][c] = Kg[r * 16 + c];
    }
    __syncthreads();

    float mx = -INFINITY, sm = 0.f;
    for (int k = 0; k < 128; k++) {
        float p0 = 0.f, p1 = 0.f, p2 = 0.f, p3 = 0.f;
        #pragma unroll
        for (int j = 0; j < 16; j++) {
            float4 kv = Ks[k][j];
            float4 qv = qr[j];
            p0 += qv.x * kv.x;
            p1 += qv.y * kv.y;
            p2 += qv.z * kv.z;
            p3 += qv.w * kv.w;
        }
        float s = (p0 + p1) + (p2 + p3);
        mx = fmaxf(mx, s);
        sm += s;
    }
    g_pM[(bh * RSPL + blockIdx.x) * CAND + t] = mx;
    g_pS[(bh * RSPL + blockIdx.x) * CAND + t] = sm;
}

// ---------------------------------------------------------------------------
// Kernel 5: combine refine partials -> exact M, final top-40.  (FROZEN)
// ---------------------------------------------------------------------------
__global__ void __launch_bounds__(CAND) finalsel_kernel()
{
    __shared__ float sv[CAND];
    __shared__ int   si[CAND];
    __shared__ float rv[CAND];
    __shared__ int   ri[CAND];

    int bh = blockIdx.x;
    int t  = threadIdx.x;

    float m = -INFINITY, s = 0.f;
    for (int sp = 0; sp < RSPL; sp++) {
        m = fmaxf(m, g_pM[(bh * RSPL + sp) * CAND + t]);
        s += g_pS[(bh * RSPL + sp) * CAND + t];
    }
    sv[t] = m - s * (1.f / (float)Lb);
    si[t] = g_cand[bh * CAND + t];
    __syncthreads();

    for (int u = 0; u < Ub; u++) {
        rv[t] = sv[t]; ri[t] = t;   // slot index for invalidation
        __syncthreads();
        for (int st = CAND / 2; st > 0; st >>= 1) {
            if (t < st) {
                float va = rv[t], vb = rv[t + st];
                int sa = ri[t], sb = ri[t + st];
                if (vb > va || (vb == va && si[sb] < si[sa])) {
                    rv[t] = vb; ri[t] = sb;
                }
            }
            __syncthreads();
        }
        if (t == 0) {
            g_top[bh * Ub + u] = si[ri[0]];
            sv[ri[0]] = -INFINITY;
        }
        __syncthreads();
    }
}

// ---------------------------------------------------------------------------
// Kernel 6: sparse attention for the selected rows (fp32)  (FROZEN)
// ---------------------------------------------------------------------------
__global__ void __launch_bounds__(128) attn_kernel(float* __restrict__ out)
{
    __shared__ float s[Lb];
    __shared__ float qs[DKb];
    __shared__ float redA[4];
    __shared__ float redB[4];
    __shared__ float accs[128];

    int u  = blockIdx.x;
    int bh = blockIdx.y;
    int b  = bh >> 4;
    int h  = bh & 15;
    int t = threadIdx.x, lane = t & 31, w = t >> 5;

    int q = g_top[bh * Ub + u];
    if (t < DKb) qs[t] = g_Q[((size_t)bh * Lb + q) * DKb + t];
    __syncthreads();

    float2 qv = *(const float2*)&qs[lane * 2];

    for (int k = w; k < Lb; k += 4) {
        const float2 kv =
            *(const float2*)(g_K + ((size_t)bh * Lb + k) * DKb + lane * 2);
        float p = qv.x * kv.x + qv.y * kv.y;
        #pragma unroll
        for (int o = 16; o; o >>= 1) p += __shfl_xor_sync(0xffffffffu, p, o);
        if (lane == 0)
            s[k] = p * 0.125f + ((k > q) ? -1e9f : 0.f);
    }
    __syncthreads();

    float lm = -INFINITY;
    for (int k = t; k < Lb; k += 128) lm = fmaxf(lm, s[k]);
    #pragma unroll
    for (int o = 16; o; o >>= 1)
        lm = fmaxf(lm, __shfl_xor_sync(0xffffffffu, lm, o));
    if (lane == 0) redA[w] = lm;
    __syncthreads();
    float mv = fmaxf(fmaxf(redA[0], redA[1]), fmaxf(redA[2], redA[3]));

    float ls = 0.f;
    for (int k = t; k < Lb; k += 128) {
        float e = __expf(s[k] - mv);
        s[k] = e;
        ls += e;
    }
    #pragma unroll
    for (int o = 16; o; o >>= 1) ls += __shfl_xor_sync(0xffffffffu, ls, o);
    if (lane == 0) redB[w] = ls;
    __syncthreads();
    float inv = 1.f / (redB[0] + redB[1] + redB[2] + redB[3]);

    float* probs = out + (size_t)Bb * Ub * Db;
    size_t po = ((size_t)(bh * Ub + u)) * Lb;
    for (int k = t; k < Lb; k += 128) probs[po + k] = s[k] * inv;

    int dk = t & 63, half = t >> 6;
    const float* Vp = g_V + (size_t)bh * Lb * DKb + dk;
    int kbase = half * (Lb / 2);
    float a0 = 0.f, a1 = 0.f, a2 = 0.f, a3 = 0.f;
    for (int k = kbase; k < kbase + Lb / 2; k += 4) {
        a0 += s[k]     * Vp[(size_t)(k)     * DKb];
        a1 += s[k + 1] * Vp[(size_t)(k + 1) * DKb];
        a2 += s[k + 2] * Vp[(size_t)(k + 2) * DKb];
        a3 += s[k + 3] * Vp[(size_t)(k + 3) * DKb];
    }
    accs[t] = (a0 + a1) + (a2 + a3);
    __syncthreads();
    if (t < 64)
        out[((size_t)(b * Ub + u)) * Db + h * DKb + t] =
            (accs[t] + accs[t + 64]) * inv;
}

// ---------------------------------------------------------------------------
extern "C" void kernel_launch(void* const* d_in, const int* in_sizes, int n_in,
                              void* d_out, int out_size)
{
    const float* query = (const float*)d_in[0];
    const float* key   = (const float*)d_in[1];
    const float* value = (const float*)d_in[2];
    const float* Wq    = (const float*)d_in[3];
    const float* bq    = (const float*)d_in[4];
    const float* Wk    = (const float*)d_in[5];
    const float* bk    = (const float*)d_in[6];
    const float* Wv    = (const float*)d_in[7];
    const float* bv    = (const float*)d_in[8];
    float* out = (float*)d_out;

    const int mscoreSmem = (2 * 128 * 68 + 4 * 128) * 4;  // 71680 B
    cudaFuncSetAttribute(mscore_tf32_kernel,
                         cudaFuncAttributeMaxDynamicSharedMemorySize, mscoreSmem);

    dim3 glqk(8, 32, 2);   // N/128, M/128, {Q,K}
    linear_fp32_qk_kernel<<<glqk, 256>>>(query, Wq, bq, key, Wk, bk);
    dim3 gl(8, 32);
    linear_tf32_kernel<<<gl, 256>>>(value, Wv, bv);     // V: tf32 3-term

    mscore_tf32_kernel<<<dim3(Lb / 128, BHb), 256, mscoreSmem>>>();
    cand_topk_kernel<<<BHb, 256>>>();
    refine_kernel<<<dim3(RSPL, BHb), CAND>>>();
    finalsel_kernel<<<BHb, CAND>>>();
    attn_kernel<<<dim3(Ub, BHb), 128>>>(out);
}

// round 14
// speedup vs baseline: 1.7154x; 1.0670x over previous
#include <cuda_runtime.h>
#include <math.h>
#include <stdint.h>

// Problem constants
#define Bb   2
#define Lb   2048
#define Db   1024
#define Hb   16
#define DKb  64
#define Ub   40
#define BHb  32
#define CAND 64          // refinement candidate count
#define RSPL 16          // key splits for refine kernel (keys/split = 128)

// Scratch (static device arrays; allocation APIs are forbidden)
__device__ float g_Q[Bb*Hb*Lb*DKb];   // [BH, L, DK]
__device__ float g_K[Bb*Hb*Lb*DKb];
__device__ float g_V[Bb*Hb*Lb*DKb];
__device__ float g_M[BHb*Lb];
__device__ int   g_cand[BHb*CAND];
__device__ float g_pM[BHb*RSPL*CAND];
__device__ float g_pS[BHb*RSPL*CAND];
__device__ int   g_top[BHb*Ub];

// ---------------------------------------------------------------------------
// Kernel 1a (Q,K merged, gridDim.z selects): fp32 SIMT GEMM with register-
// staged double buffering. Per-output-element FFMA chain is k-ascending and
// IDENTICAL to the round-2/11/12/13 passing kernels -> g_Q/g_K bit-exact.
// (FROZEN)
// ---------------------------------------------------------------------------
__global__ void __launch_bounds__(256, 2) linear_fp32_qk_kernel(
    const float* __restrict__ Xq, const float* __restrict__ Wq_, const float* __restrict__ bq_,
    const float* __restrict__ Xk, const float* __restrict__ Wk_, const float* __restrict__ bk_)
{
    __shared__ float As[2][16][132];   // [buf][kk][m]
    __shared__ float Bs[2][16][132];   // [buf][kk][n]

    const float *X, *W, *bias;
    float* Y;
    if (blockIdx.z == 0) { X = Xq; W = Wq_; bias = bq_; Y = g_Q; }
    else                 { X = Xk; W = Wk_; bias = bk_; Y = g_K; }

    int tid = threadIdx.x;
    int m0 = blockIdx.y * 128;
    int n0 = blockIdx.x * 128;
    int tx = tid & 15;        // n direction
    int ty = tid >> 4;        // m direction

    float acc[8][8];
    #pragma unroll
    for (int i = 0; i < 8; i++)
        #pragma unroll
        for (int j = 0; j < 8; j++) acc[i][j] = 0.f;

    float xr[8], wr[8];
    int kkq[8], rq[8];
    #pragma unroll
    for (int i = 0; i < 8; i++) {
        int lin = tid + i * 256;
        kkq[i] = lin & 15;
        rq[i]  = lin >> 4;
    }

    // prologue: tile 0 -> regs -> smem buf 0
    #pragma unroll
    for (int i = 0; i < 8; i++) {
        xr[i] = X[(size_t)(m0 + rq[i]) * 1024 + kkq[i]];
        wr[i] = W[(size_t)(n0 + rq[i]) * 1024 + kkq[i]];
    }
    #pragma unroll
    for (int i = 0; i < 8; i++) {
        As[0][kkq[i]][rq[i]] = xr[i];
        Bs[0][kkq[i]][rq[i]] = wr[i];
    }
    __syncthreads();

    for (int t = 0; t < 64; t++) {
        int buf = t & 1;
        if (t + 1 < 64) {
            int k0 = (t + 1) * 16;
            #pragma unroll
            for (int i = 0; i < 8; i++) {
                xr[i] = X[(size_t)(m0 + rq[i]) * 1024 + k0 + kkq[i]];
                wr[i] = W[(size_t)(n0 + rq[i]) * 1024 + k0 + kkq[i]];
            }
        }

        #pragma unroll
        for (int kk = 0; kk < 16; kk++) {
            float4 a0 = *(const float4*)&As[buf][kk][ty * 8];
            float4 a1 = *(const float4*)&As[buf][kk][ty * 8 + 4];
            float4 b0 = *(const float4*)&Bs[buf][kk][tx * 8];
            float4 b1 = *(const float4*)&Bs[buf][kk][tx * 8 + 4];
            float a[8] = {a0.x,a0.y,a0.z,a0.w,a1.x,a1.y,a1.z,a1.w};
            float b[8] = {b0.x,b0.y,b0.z,b0.w,b1.x,b1.y,b1.z,b1.w};
            #pragma unroll
            for (int i = 0; i < 8; i++)
                #pragma unroll
                for (int j = 0; j < 8; j++)
                    acc[i][j] += a[i] * b[j];
        }

        if (t + 1 < 64) {
            #pragma unroll
            for (int i = 0; i < 8; i++) {
                As[buf ^ 1][kkq[i]][rq[i]] = xr[i];
                Bs[buf ^ 1][kkq[i]][rq[i]] = wr[i];
            }
        }
        __syncthreads();
    }

    #pragma unroll
    for (int i = 0; i < 8; i++) {
        int m  = m0 + ty * 8 + i;
        int bb = m >> 11;
        int l  = m & 2047;
        #pragma unroll
        for (int j = 0; j < 8; j++) {
            int n  = n0 + tx * 8 + j;
            int h  = n >> 6;
            int dk = n & 63;
            size_t off = (((size_t)(bb * Hb + h) * Lb) + l) * DKb + dk;
            Y[off] = acc[i][j] + bias[n];
        }
    }
}

// ---------------------------------------------------------------------------
// tf32 helpers. PTX fragment mapping for m16n8k8 tf32 (gr=lane>>2, gc=lane&3):
//   A: a0=(gr,gc) a1=(gr+8,gc) a2=(gr,gc+4) a3=(gr+8,gc+4)
//   B: b0=(k=gc,n=gr) b1=(k=gc+4,n=gr)
//   C: c0=(gr,2gc) c1=(gr,2gc+1) c2=(gr+8,2gc) c3=(gr+8,2gc+1)
// ---------------------------------------------------------------------------
__device__ __forceinline__ uint32_t tf32_of(float v) {
    uint32_t r;
    asm("cvt.rna.tf32.f32 %0, %1;" : "=r"(r) : "f"(v));
    return r;
}
__device__ __forceinline__ void split_tf32(float v, uint32_t& hi, uint32_t& lo) {
    hi = tf32_of(v);
    lo = tf32_of(v - __uint_as_float(hi));
}
__device__ __forceinline__ void mma8(float* c,
                                     uint32_t a0, uint32_t a1, uint32_t a2, uint32_t a3,
                                     uint32_t b0, uint32_t b1) {
    asm volatile(
        "mma.sync.aligned.m16n8k8.row.col.f32.tf32.tf32.f32 "
        "{%0,%1,%2,%3}, {%4,%5,%6,%7}, {%8,%9}, {%0,%1,%2,%3};\n"
        : "+f"(c[0]), "+f"(c[1]), "+f"(c[2]), "+f"(c[3])
        : "r"(a0), "r"(a1), "r"(a2), "r"(a3), "r"(b0), "r"(b1));
}

// ---------------------------------------------------------------------------
// Kernel 1b (V): 3xTF32 split mma GEMM. V only needs ~1e-3 accuracy. (FROZEN)
// ---------------------------------------------------------------------------
__global__ void __launch_bounds__(256) linear_tf32_kernel(
    const float* __restrict__ X, const float* __restrict__ W,
    const float* __restrict__ bias)
{
    __shared__ float Xs[128][36];
    __shared__ float Ws[128][36];
    float* Y = g_V;

    int tid  = threadIdx.x;
    int lane = tid & 31, warp = tid >> 5;
    int wm = warp >> 1, wn = warp & 1;
    int gr = lane >> 2, gc = lane & 3;
    int m0 = blockIdx.y * 128, n0 = blockIdx.x * 128;

    float acc[2][8][4];
    #pragma unroll
    for (int mt = 0; mt < 2; mt++)
        #pragma unroll
        for (int nt = 0; nt < 8; nt++)
            #pragma unroll
            for (int r = 0; r < 4; r++) acc[mt][nt][r] = 0.f;

    int lr = tid >> 3, lc = (tid & 7) * 4;

    for (int k0 = 0; k0 < Db; k0 += 32) {
        __syncthreads();
        #pragma unroll
        for (int i = 0; i < 4; i++) {
            int r = lr + i * 32;
            *(float4*)&Xs[r][lc] = *(const float4*)&X[(size_t)(m0 + r) * Db + k0 + lc];
            *(float4*)&Ws[r][lc] = *(const float4*)&W[(size_t)(n0 + r) * Db + k0 + lc];
        }
        __syncthreads();

        #pragma unroll
        for (int k8 = 0; k8 < 32; k8 += 8) {
            uint32_t ah[2][4], al[2][4];
            #pragma unroll
            for (int mt = 0; mt < 2; mt++) {
                int rb = wm * 32 + mt * 16;
                split_tf32(Xs[rb + gr][k8 + gc],         ah[mt][0], al[mt][0]);
                split_tf32(Xs[rb + gr + 8][k8 + gc],     ah[mt][1], al[mt][1]);
                split_tf32(Xs[rb + gr][k8 + gc + 4],     ah[mt][2], al[mt][2]);
                split_tf32(Xs[rb + gr + 8][k8 + gc + 4], ah[mt][3], al[mt][3]);
            }
            #pragma unroll
            for (int nt = 0; nt < 8; nt++) {
                int nb = wn * 64 + nt * 8;
                uint32_t bh0, bl0, bh1, bl1;
                split_tf32(Ws[nb + gr][k8 + gc],     bh0, bl0);
                split_tf32(Ws[nb + gr][k8 + gc + 4], bh1, bl1);
                #pragma unroll
                for (int mt = 0; mt < 2; mt++) {
                    mma8(acc[mt][nt], ah[mt][0], ah[mt][1], ah[mt][2], ah[mt][3], bh0, bh1);
                    mma8(acc[mt][nt], ah[mt][0], ah[mt][1], ah[mt][2], ah[mt][3], bl0, bl1);
                    mma8(acc[mt][nt], al[mt][0], al[mt][1], al[mt][2], al[mt][3], bh0, bh1);
                }
            }
        }
    }

    #pragma unroll
    for (int mt = 0; mt < 2; mt++) {
        int m_lo = m0 + wm * 32 + mt * 16 + gr;
        #pragma unroll
        for (int nt = 0; nt < 8; nt++) {
            int n = n0 + wn * 64 + nt * 8 + 2 * gc;
            float2 bv = *(const float2*)&bias[n];
            int h = n >> 6, dk = n & 63;
            {
                int m = m_lo, b = m >> 11, l = m & 2047;
                float2 o; o.x = acc[mt][nt][0] + bv.x; o.y = acc[mt][nt][1] + bv.y;
                *(float2*)&Y[(((size_t)(b * Hb + h) * Lb) + l) * DKb + dk] = o;
            }
            {
                int m = m_lo + 8, b = m >> 11, l = m & 2047;
                float2 o; o.x = acc[mt][nt][2] + bv.x; o.y = acc[mt][nt][3] + bv.y;
                *(float2*)&Y[(((size_t)(b * Hb + h) * Lb) + l) * DKb + dk] = o;
            }
        }
    }
}

// ---------------------------------------------------------------------------
// Kernel 2: approx M[bh,q] = max_k(Q.K) - mean_k(Q.K), single-pass tf32,
// cvt hoisted to tile-load time.  (FROZEN from R13)
// ---------------------------------------------------------------------------
__global__ void __launch_bounds__(256) mscore_tf32_kernel()
{
    extern __shared__ float smdyn[];
    float (*Qs)[68] = (float (*)[68])smdyn;
    float (*Ks)[68] = (float (*)[68])(smdyn + 128 * 68);
    float* rM = smdyn + 2 * 128 * 68;   // [2][128]
    float* rS = rM + 2 * 128;           // [2][128]

    int bh = blockIdx.y;
    int q0 = blockIdx.x * 128;
    int tid  = threadIdx.x;
    int lane = tid & 31, warp = tid >> 5;
    int wm = warp >> 1, wn = warp & 1;
    int gr = lane >> 2, gc = lane & 3;

    const float* Qg = g_Q + (size_t)bh * Lb * DKb;
    const float* Kg = g_K + (size_t)bh * Lb * DKb;

    int lr = tid >> 4, lc = (tid & 15) * 4;
    #pragma unroll
    for (int i = 0; i < 8; i++) {
        int r = lr + i * 16;
        float4 v = *(const float4*)&Qg[(size_t)(q0 + r) * DKb + lc];
        v.x = __uint_as_float(tf32_of(v.x));
        v.y = __uint_as_float(tf32_of(v.y));
        v.z = __uint_as_float(tf32_of(v.z));
        v.w = __uint_as_float(tf32_of(v.w));
        *(float4*)&Qs[r][lc] = v;
    }

    float rmax[2][2], rsum[2][2];
    #pragma unroll
    for (int a = 0; a < 2; a++)
        #pragma unroll
        for (int b = 0; b < 2; b++) { rmax[a][b] = -INFINITY; rsum[a][b] = 0.f; }

    float acc[2][8][4];
    #pragma unroll
    for (int mt = 0; mt < 2; mt++)
        #pragma unroll
        for (int nt = 0; nt < 8; nt++)
            #pragma unroll
            for (int r = 0; r < 4; r++) acc[mt][nt][r] = 0.f;

    for (int kt = 0; kt < Lb; kt += 128) {
        __syncthreads();
        #pragma unroll
        for (int i = 0; i < 8; i++) {
            int r = lr + i * 16;
            float4 v = *(const float4*)&Kg[(size_t)(kt + r) * DKb + lc];
            v.x = __uint_as_float(tf32_of(v.x));
            v.y = __uint_as_float(tf32_of(v.y));
            v.z = __uint_as_float(tf32_of(v.z));
            v.w = __uint_as_float(tf32_of(v.w));
            *(float4*)&Ks[r][lc] = v;
        }
        __syncthreads();

        #pragma unroll
        for (int k8 = 0; k8 < 64; k8 += 8) {
            uint32_t ah[2][4];
            #pragma unroll
            for (int mt = 0; mt < 2; mt++) {
                int rb = wm * 32 + mt * 16;
                ah[mt][0] = __float_as_uint(Qs[rb + gr][k8 + gc]);
                ah[mt][1] = __float_as_uint(Qs[rb + gr + 8][k8 + gc]);
                ah[mt][2] = __float_as_uint(Qs[rb + gr][k8 + gc + 4]);
                ah[mt][3] = __float_as_uint(Qs[rb + gr + 8][k8 + gc + 4]);
            }
            #pragma unroll
            for (int nt = 0; nt < 8; nt++) {
                int nb = wn * 64 + nt * 8;
                uint32_t bh0 = __float_as_uint(Ks[nb + gr][k8 + gc]);
                uint32_t bh1 = __float_as_uint(Ks[nb + gr][k8 + gc + 4]);
                #pragma unroll
                for (int mt = 0; mt < 2; mt++)
                    mma8(acc[mt][nt], ah[mt][0], ah[mt][1], ah[mt][2], ah[mt][3], bh0, bh1);
            }
        }

        #pragma unroll
        for (int mt = 0; mt < 2; mt++) {
            float mx0 = -INFINITY, mx1 = -INFINITY, s0 = 0.f, s1 = 0.f;
            #pragma unroll
            for (int nt = 0; nt < 8; nt++) {
                mx0 = fmaxf(mx0, fmaxf(acc[mt][nt][0], acc[mt][nt][1]));
                mx1 = fmaxf(mx1, fmaxf(acc[mt][nt][2], acc[mt][nt][3]));
                s0 += acc[mt][nt][0] + acc[mt][nt][1];
                s1 += acc[mt][nt][2] + acc[mt][nt][3];
                acc[mt][nt][0] = 0.f; acc[mt][nt][1] = 0.f;
                acc[mt][nt][2] = 0.f; acc[mt][nt][3] = 0.f;
            }
            rmax[mt][0] = fmaxf(rmax[mt][0], mx0);
            rmax[mt][1] = fmaxf(rmax[mt][1], mx1);
            rsum[mt][0] += s0;
            rsum[mt][1] += s1;
        }
    }

    #pragma unroll
    for (int mt = 0; mt < 2; mt++)
        #pragma unroll
        for (int hf = 0; hf < 2; hf++) {
            float m = rmax[mt][hf], s = rsum[mt][hf];
            #pragma unroll
            for (int o = 1; o < 4; o <<= 1) {
                m = fmaxf(m, __shfl_xor_sync(0xffffffffu, m, o));
                s += __shfl_xor_sync(0xffffffffu, s, o);
            }
            if (gc == 0) {
                int row = wm * 32 + mt * 16 + hf * 8 + gr;
                rM[wn * 128 + row] = m;
                rS[wn * 128 + row] = s;
            }
        }
    __syncthreads();
    if (tid < 128) {
        float m = fmaxf(rM[tid], rM[128 + tid]);
        float s = rS[tid] + rS[128 + tid];
        g_M[bh * Lb + q0 + tid] = m - s * (1.f / (float)Lb);
    }
}

// ---------------------------------------------------------------------------
// Kernel 3: candidate selection via MSB-first radix select.
// Finds the exact 64th-largest approx-M key, compacts {key > T} then fills
// with {key == T} ties (arbitrary order) to exactly CAND entries.
// Set semantics identical to iterative argmax (ties at the rank-64 boundary
// are far below true rank-40 -> any tie resolution keeps the superset valid).
// ---------------------------------------------------------------------------
__global__ void __launch_bounds__(256) cand_select_kernel()
{
    __shared__ unsigned int ukeys[Lb];      // 8 KB
    __shared__ unsigned int hist[256];
    __shared__ unsigned int prefix_sh;
    __shared__ int remaining_sh;
    __shared__ int cntHigh, cntTie;

    int bh = blockIdx.x;
    int t  = threadIdx.x;

    // monotone map: ascending uint order == ascending float order
    for (int i = t; i < Lb; i += 256) {
        unsigned int u = __float_as_uint(g_M[bh * Lb + i]);
        ukeys[i] = (u & 0x80000000u) ? ~u : (u | 0x80000000u);
    }
    if (t == 0) { cntHigh = 0; cntTie = 0; }
    __syncthreads();

    unsigned int prefix = 0;
    int K = CAND;                       // rank from the top within prefix group
    #pragma unroll
    for (int pass = 0; pass < 4; pass++) {
        int shift = 24 - pass * 8;
        hist[t] = 0;                    // 256 threads, 256 bins
        __syncthreads();
        unsigned int mask = (pass == 0) ? 0u : (0xFFFFFFFFu << (32 - 8 * pass));
        for (int i = t; i < Lb; i += 256) {
            unsigned int u = ukeys[i];
            if ((u & mask) == prefix)
                atomicAdd(&hist[(u >> shift) & 0xFF], 1u);
        }
        __syncthreads();
        if (t == 0) {
            int rem = K;
            for (int b = 255; b >= 0; b--) {
                int c = (int)hist[b];
                if (c >= rem) {
                    prefix_sh = prefix | ((unsigned int)b << shift);
                    remaining_sh = rem;
                    break;
                }
                rem -= c;
            }
        }
        __syncthreads();
        prefix = prefix_sh;
        K = remaining_sh;
        __syncthreads();
    }

    unsigned int T = prefix;            // exact CAND-th largest key
    // strict-greater first
    for (int i = t; i < Lb; i += 256) {
        if (ukeys[i] > T) {
            int p = atomicAdd(&cntHigh, 1);
            g_cand[bh * CAND + p] = i;
        }
    }
    __syncthreads();
    int base = cntHigh;                 // == CAND - K
    for (int i = t; i < Lb; i += 256) {
        if (ukeys[i] == T) {
            int p = atomicAdd(&cntTie, 1);
            if (base + p < CAND)
                g_cand[bh * CAND + base + p] = i;
        }
    }
}

// ---------------------------------------------------------------------------
// Kernel 4: exact fp32 refinement of M for the candidates.  (FROZEN)
// ---------------------------------------------------------------------------
__global__ void __launch_bounds__(CAND) refine_kernel()
{
    __shared__ float4 Ks[128][16];
    int bh = blockIdx.y;
    int s0 = blockIdx.x * 128;
    int t  = threadIdx.x;

    int qi = g_cand[bh * CAND + t];
    const float4* Qp = (const float4*)(g_Q + ((size_t)bh * Lb + qi) * DKb);
    float4 qr[16];
    #pragma unroll
    for (int j = 0; j < 16; j++) qr[j] = Qp[j];

    const float4* Kg = (const float4*)(g_K + ((size_t)bh * Lb + s0) * DKb);
    #pragma unroll
    for (int i = 0; i < 32; i++) {
        int lin = t + i * CAND;
        int r = lin >> 4, c = lin & 15;
        Ks[r][c] = Kg[r * 16 + c];
    }
    __syncthreads();

    float mx = -INFINITY, sm = 0.f;
    for (int k = 0; k < 128; k++) {
        float p0 = 0.f, p1 = 0.f, p2 = 0.f, p3 = 0.f;
        #pragma unroll
        for (int j = 0; j < 16; j++) {
            float4 kv = Ks[k][j];
            float4 qv = qr[j];
            p0 += qv.x * kv.x;
            p1 += qv.y * kv.y;
            p2 += qv.z * kv.z;
            p3 += qv.w * kv.w;
        }
        float s = (p0 + p1) + (p2 + p3);
        mx = fmaxf(mx, s);
        sm += s;
    }
    g_pM[(bh * RSPL + blockIdx.x) * CAND + t] = mx;
    g_pS[(bh * RSPL + blockIdx.x) * CAND + t] = sm;
}

// ---------------------------------------------------------------------------
// Kernel 5: combine refine partials -> exact M, final top-40.  (FROZEN)
// ---------------------------------------------------------------------------
__global__ void __launch_bounds__(CAND) finalsel_kernel()
{
    __shared__ float sv[CAND];
    __shared__ int   si[CAND];
    __shared__ float rv[CAND];
    __shared__ int   ri[CAND];

    int bh = blockIdx.x;
    int t  = threadIdx.x;

    float m = -INFINITY, s = 0.f;
    for (int sp = 0; sp < RSPL; sp++) {
        m = fmaxf(m, g_pM[(bh * RSPL + sp) * CAND + t]);
        s += g_pS[(bh * RSPL + sp) * CAND + t];
    }
    sv[t] = m - s * (1.f / (float)Lb);
    si[t] = g_cand[bh * CAND + t];
    __syncthreads();

    for (int u = 0; u < Ub; u++) {
        rv[t] = sv[t]; ri[t] = t;   // slot index for invalidation
        __syncthreads();
        for (int st = CAND / 2; st > 0; st >>= 1) {
            if (t < st) {
                float va = rv[t], vb = rv[t + st];
                int sa = ri[t], sb = ri[t + st];
                if (vb > va || (vb == va && si[sb] < si[sa])) {
                    rv[t] = vb; ri[t] = sb;
                }
            }
            __syncthreads();
        }
        if (t == 0) {
            g_top[bh * Ub + u] = si[ri[0]];
            sv[ri[0]] = -INFINITY;
        }
        __syncthreads();
    }
}

// ---------------------------------------------------------------------------
// Kernel 6: sparse attention. Score phase: K tile staged in SMEM (stride 68
// floats -> row-per-lane LDS.128 conflict-free), q row in registers, one dot
// per thread per tile. Softmax + P@V unchanged from the passing kernel.
// ---------------------------------------------------------------------------
__global__ void __launch_bounds__(128) attn_kernel(float* __restrict__ out)
{
    __shared__ float s[Lb];             // 8 KB
    __shared__ float Kt[128][68];       // 34 KB
    __shared__ float redA[4];
    __shared__ float redB[4];
    __shared__ float accs[128];

    int u  = blockIdx.x;
    int bh = blockIdx.y;
    int b  = bh >> 4;
    int h  = bh & 15;
    int t = threadIdx.x, lane = t & 31, w = t >> 5;

    int q = g_top[bh * Ub + u];

    // q row into registers (all threads same row; L1 broadcast)
    float4 qr[16];
    const float4* Qp = (const float4*)(g_Q + ((size_t)bh * Lb + q) * DKb);
    #pragma unroll
    for (int j = 0; j < 16; j++) qr[j] = Qp[j];

    const float4* Kg4 = (const float4*)(g_K + (size_t)bh * Lb * DKb);

    for (int kt = 0; kt < Lb; kt += 128) {
        __syncthreads();
        #pragma unroll
        for (int i = 0; i < 16; i++) {
            int lin = t + i * 128;
            int r = lin >> 4, c = lin & 15;
            *(float4*)&Kt[r][c * 4] = Kg4[(size_t)(kt + r) * 16 + c];
        }
        __syncthreads();

        int k = kt + t;                 // one row per thread (t < 128)
        float p0 = 0.f, p1 = 0.f, p2 = 0.f, p3 = 0.f;
        #pragma unroll
        for (int j = 0; j < 16; j++) {
            float4 kv = *(const float4*)&Kt[t][j * 4];
            float4 qv = qr[j];
            p0 += qv.x * kv.x;
            p1 += qv.y * kv.y;
            p2 += qv.z * kv.z;
            p3 += qv.w * kv.w;
        }
        float dot = (p0 + p1) + (p2 + p3);
        s[k] = dot * 0.125f + ((k > q) ? -1e9f : 0.f);
        // second row for this thread (rows 128 threads cover 128 of 128) — none; tile is 128 rows
    }
    __syncthreads();

    float lm = -INFINITY;
    for (int k = t; k < Lb; k += 128) lm = fmaxf(lm, s[k]);
    #pragma unroll
    for (int o = 16; o; o >>= 1)
        lm = fmaxf(lm, __shfl_xor_sync(0xffffffffu, lm, o));
    if (lane == 0) redA[w] = lm;
    __syncthreads();
    float mv = fmaxf(fmaxf(redA[0], redA[1]), fmaxf(redA[2], redA[3]));

    float ls = 0.f;
    for (int k = t; k < Lb; k += 128) {
        float e = __expf(s[k] - mv);
        s[k] = e;
        ls += e;
    }
    #pragma unroll
    for (int o = 16; o; o >>= 1) ls += __shfl_xor_sync(0xffffffffu, ls, o);
    if (lane == 0) redB[w] = ls;
    __syncthreads();
    float inv = 1.f / (redB[0] + redB[1] + redB[2] + redB[3]);

    float* probs = out + (size_t)Bb * Ub * Db;
    size_t po = ((size_t)(bh * Ub + u)) * Lb;
    for (int k = t; k < Lb; k += 128) probs[po + k] = s[k] * inv;

    int dk = t & 63, half = t >> 6;
    const float* Vp = g_V + (size_t)bh * Lb * DKb + dk;
    int kbase = half * (Lb / 2);
    float a0 = 0.f, a1 = 0.f, a2 = 0.f, a3 = 0.f;
    for (int k = kbase; k < kbase + Lb / 2; k += 4) {
        a0 += s[k]     * Vp[(size_t)(k)     * DKb];
        a1 += s[k + 1] * Vp[(size_t)(k + 1) * DKb];
        a2 += s[k + 2] * Vp[(size_t)(k + 2) * DKb];
        a3 += s[k + 3] * Vp[(size_t)(k + 3) * DKb];
    }
    accs[t] = (a0 + a1) + (a2 + a3);
    __syncthreads();
    if (t < 64)
        out[((size_t)(b * Ub + u)) * Db + h * DKb + t] =
            (accs[t] + accs[t + 64]) * inv;
}

// ---------------------------------------------------------------------------
extern "C" void kernel_launch(void* const* d_in, const int* in_sizes, int n_in,
                              void* d_out, int out_size)
{
    const float* query = (const float*)d_in[0];
    const float* key   = (const float*)d_in[1];
    const float* value = (const float*)d_in[2];
    const float* Wq    = (const float*)d_in[3];
    const float* bq    = (const float*)d_in[4];
    const float* Wk    = (const float*)d_in[5];
    const float* bk    = (const float*)d_in[6];
    const float* Wv    = (const float*)d_in[7];
    const float* bv    = (const float*)d_in[8];
    float* out = (float*)d_out;

    const int mscoreSmem = (2 * 128 * 68 + 4 * 128) * 4;  // 71680 B
    cudaFuncSetAttribute(mscore_tf32_kernel,
                         cudaFuncAttributeMaxDynamicSharedMemorySize, mscoreSmem);

    dim3 glqk(8, 32, 2);   // N/128, M/128, {Q,K}
    linear_fp32_qk_kernel<<<glqk, 256>>>(query, Wq, bq, key, Wk, bk);
    dim3 gl(8, 32);
    linear_tf32_kernel<<<gl, 256>>>(value, Wv, bv);     // V: tf32 3-term

    mscore_tf32_kernel<<<dim3(Lb / 128, BHb), 256, mscoreSmem>>>();
    cand_select_kernel<<<BHb, 256>>>();
    refine_kernel<<<dim3(RSPL, BHb), CAND>>>();
    finalsel_kernel<<<BHb, CAND>>>();
    attn_kernel<<<dim3(Ub, BHb), 128>>>(out);
}

// round 17
// speedup vs baseline: 1.8034x; 1.0513x over previous
#include <cuda_runtime.h>
#include <math.h>
#include <stdint.h>

// Problem constants
#define Bb   2
#define Lb   2048
#define Db   1024
#define Hb   16
#define DKb  64
#define Ub   40
#define BHb  32
#define CAND 64          // refinement candidate count
#define RSPL 16          // key splits for refine kernel (keys/split = 128)

// Scratch (static device arrays; allocation APIs are forbidden)
__device__ float g_Q[Bb*Hb*Lb*DKb];   // [BH, L, DK]
__device__ float g_K[Bb*Hb*Lb*DKb];
__device__ float g_V[Bb*Hb*Lb*DKb];
__device__ float g_M[BHb*Lb];
__device__ int   g_cand[BHb*CAND];
__device__ float g_pM[BHb*RSPL*CAND];
__device__ float g_pS[BHb*RSPL*CAND];
__device__ int   g_top[BHb*Ub];

// ---------------------------------------------------------------------------
// tf32 helpers. PTX fragment mapping for m16n8k8 tf32 (gr=lane>>2, gc=lane&3):
//   A: a0=(gr,gc) a1=(gr+8,gc) a2=(gr,gc+4) a3=(gr+8,gc+4)
//   B: b0=(k=gc,n=gr) b1=(k=gc+4,n=gr)
//   C: c0=(gr,2gc) c1=(gr,2gc+1) c2=(gr+8,2gc) c3=(gr+8,2gc+1)
// ---------------------------------------------------------------------------
__device__ __forceinline__ uint32_t tf32_of(float v) {
    uint32_t r;
    asm("cvt.rna.tf32.f32 %0, %1;" : "=r"(r) : "f"(v));
    return r;
}
__device__ __forceinline__ void split_tf32(float v, uint32_t& hi, uint32_t& lo) {
    hi = tf32_of(v);
    lo = tf32_of(v - __uint_as_float(hi));
}
__device__ __forceinline__ void mma8(float* c,
                                     uint32_t a0, uint32_t a1, uint32_t a2, uint32_t a3,
                                     uint32_t b0, uint32_t b1) {
    asm volatile(
        "mma.sync.aligned.m16n8k8.row.col.f32.tf32.tf32.f32 "
        "{%0,%1,%2,%3}, {%4,%5,%6,%7}, {%8,%9}, {%0,%1,%2,%3};\n"
        : "+f"(c[0]), "+f"(c[1]), "+f"(c[2]), "+f"(c[3])
        : "r"(a0), "r"(a1), "r"(a2), "r"(a3), "r"(b0), "r"(b1));
}

// ---------------------------------------------------------------------------
// Kernel 1 (FUSED QKV): gridDim.z = 3.
//   z==0 -> Q, z==1 -> K : fp32 SIMT GEMM, per-element FFMA chain k-ascending,
//           byte-identical to the R11-R14 passing kernels -> g_Q/g_K bit-exact.
//   z==2 -> V : 3xTF32 split mma GEMM (~1e-5 accuracy; V tolerance 1e-3).
// Fusing packs V's 256 blocks into the QK tail wave (512 blocks / 296 slots),
// and the paths use disjoint pipes (FFMA vs tensor).
// ---------------------------------------------------------------------------
__global__ void __launch_bounds__(256, 2) linear_fused_kernel(
    const float* __restrict__ Xq, const float* __restrict__ Wq_, const float* __restrict__ bq_,
    const float* __restrict__ Xk, const float* __restrict__ Wk_, const float* __restrict__ bk_,
    const float* __restrict__ Xv, const float* __restrict__ Wv_, const float* __restrict__ bv_)
{
    __shared__ __align__(16) char smbuf[36864];   // union of both paths

    int tid = threadIdx.x;
    int m0 = blockIdx.y * 128;
    int n0 = blockIdx.x * 128;

    if (blockIdx.z < 2) {
        // ---------------- fp32 QK path (FROZEN arithmetic) ----------------
        float (*As)[16][132] = (float (*)[16][132])smbuf;            // [2][16][132]
        float (*Bs)[16][132] = (float (*)[16][132])(smbuf + 16896);

        const float *X, *W, *bias;
        float* Y;
        if (blockIdx.z == 0) { X = Xq; W = Wq_; bias = bq_; Y = g_Q; }
        else                 { X = Xk; W = Wk_; bias = bk_; Y = g_K; }

        int tx = tid & 15;        // n direction
        int ty = tid >> 4;        // m direction

        float acc[8][8];
        #pragma unroll
        for (int i = 0; i < 8; i++)
            #pragma unroll
            for (int j = 0; j < 8; j++) acc[i][j] = 0.f;

        float xr[8], wr[8];
        int kkq[8], rq[8];
        #pragma unroll
        for (int i = 0; i < 8; i++) {
            int lin = tid + i * 256;
            kkq[i] = lin & 15;
            rq[i]  = lin >> 4;
        }

        #pragma unroll
        for (int i = 0; i < 8; i++) {
            xr[i] = X[(size_t)(m0 + rq[i]) * 1024 + kkq[i]];
            wr[i] = W[(size_t)(n0 + rq[i]) * 1024 + kkq[i]];
        }
        #pragma unroll
        for (int i = 0; i < 8; i++) {
            As[0][kkq[i]][rq[i]] = xr[i];
            Bs[0][kkq[i]][rq[i]] = wr[i];
        }
        __syncthreads();

        for (int t = 0; t < 64; t++) {
            int buf = t & 1;
            if (t + 1 < 64) {
                int k0 = (t + 1) * 16;
                #pragma unroll
                for (int i = 0; i < 8; i++) {
                    xr[i] = X[(size_t)(m0 + rq[i]) * 1024 + k0 + kkq[i]];
                    wr[i] = W[(size_t)(n0 + rq[i]) * 1024 + k0 + kkq[i]];
                }
            }

            #pragma unroll
            for (int kk = 0; kk < 16; kk++) {
                float4 a0 = *(const float4*)&As[buf][kk][ty * 8];
                float4 a1 = *(const float4*)&As[buf][kk][ty * 8 + 4];
                float4 b0 = *(const float4*)&Bs[buf][kk][tx * 8];
                float4 b1 = *(const float4*)&Bs[buf][kk][tx * 8 + 4];
                float a[8] = {a0.x,a0.y,a0.z,a0.w,a1.x,a1.y,a1.z,a1.w};
                float b[8] = {b0.x,b0.y,b0.z,b0.w,b1.x,b1.y,b1.z,b1.w};
                #pragma unroll
                for (int i = 0; i < 8; i++)
                    #pragma unroll
                    for (int j = 0; j < 8; j++)
                        acc[i][j] += a[i] * b[j];
            }

            if (t + 1 < 64) {
                #pragma unroll
                for (int i = 0; i < 8; i++) {
                    As[buf ^ 1][kkq[i]][rq[i]] = xr[i];
                    Bs[buf ^ 1][kkq[i]][rq[i]] = wr[i];
                }
            }
            __syncthreads();
        }

        #pragma unroll
        for (int i = 0; i < 8; i++) {
            int m  = m0 + ty * 8 + i;
            int bb = m >> 11;
            int l  = m & 2047;
            #pragma unroll
            for (int j = 0; j < 8; j++) {
                int n  = n0 + tx * 8 + j;
                int h  = n >> 6;
                int dk = n & 63;
                size_t off = (((size_t)(bb * Hb + h) * Lb) + l) * DKb + dk;
                Y[off] = acc[i][j] + bias[n];
            }
        }
    } else {
        // ---------------- tf32 V path (3-term split) ----------------
        float (*Xs)[36] = (float (*)[36])smbuf;             // [128][36]
        float (*Ws)[36] = (float (*)[36])(smbuf + 18432);
        const float* X = Xv; const float* W = Wv_; const float* bias = bv_;
        float* Y = g_V;

        int lane = tid & 31, warp = tid >> 5;
        int wm = warp >> 1, wn = warp & 1;
        int gr = lane >> 2, gc = lane & 3;

        float acc[2][8][4];
        #pragma unroll
        for (int mt = 0; mt < 2; mt++)
            #pragma unroll
            for (int nt = 0; nt < 8; nt++)
                #pragma unroll
                for (int r = 0; r < 4; r++) acc[mt][nt][r] = 0.f;

        int lr = tid >> 3, lc = (tid & 7) * 4;

        for (int k0 = 0; k0 < Db; k0 += 32) {
            __syncthreads();
            #pragma unroll
            for (int i = 0; i < 4; i++) {
                int r = lr + i * 32;
                *(float4*)&Xs[r][lc] = *(const float4*)&X[(size_t)(m0 + r) * Db + k0 + lc];
                *(float4*)&Ws[r][lc] = *(const float4*)&W[(size_t)(n0 + r) * Db + k0 + lc];
            }
            __syncthreads();

            #pragma unroll
            for (int k8 = 0; k8 < 32; k8 += 8) {
                uint32_t ah[2][4], al[2][4];
                #pragma unroll
                for (int mt = 0; mt < 2; mt++) {
                    int rb = wm * 32 + mt * 16;
                    split_tf32(Xs[rb + gr][k8 + gc],         ah[mt][0], al[mt][0]);
                    split_tf32(Xs[rb + gr + 8][k8 + gc],     ah[mt][1], al[mt][1]);
                    split_tf32(Xs[rb + gr][k8 + gc + 4],     ah[mt][2], al[mt][2]);
                    split_tf32(Xs[rb + gr + 8][k8 + gc + 4], ah[mt][3], al[mt][3]);
                }
                #pragma unroll
                for (int nt = 0; nt < 8; nt++) {
                    int nb = wn * 64 + nt * 8;
                    uint32_t bh0, bl0, bh1, bl1;
                    split_tf32(Ws[nb + gr][k8 + gc],     bh0, bl0);
                    split_tf32(Ws[nb + gr][k8 + gc + 4], bh1, bl1);
                    #pragma unroll
                    for (int mt = 0; mt < 2; mt++) {
                        mma8(acc[mt][nt], ah[mt][0], ah[mt][1], ah[mt][2], ah[mt][3], bh0, bh1);
                        mma8(acc[mt][nt], ah[mt][0], ah[mt][1], ah[mt][2], ah[mt][3], bl0, bl1);
                        mma8(acc[mt][nt], al[mt][0], al[mt][1], al[mt][2], al[mt][3], bh0, bh1);
                    }
                }
            }
        }

        #pragma unroll
        for (int mt = 0; mt < 2; mt++) {
            int m_lo = m0 + wm * 32 + mt * 16 + gr;
            #pragma unroll
            for (int nt = 0; nt < 8; nt++) {
                int n = n0 + wn * 64 + nt * 8 + 2 * gc;
                float2 bv2 = *(const float2*)&bias[n];
                int h = n >> 6, dk = n & 63;
                {
                    int m = m_lo, b = m >> 11, l = m & 2047;
                    float2 o; o.x = acc[mt][nt][0] + bv2.x; o.y = acc[mt][nt][1] + bv2.y;
                    *(float2*)&Y[(((size_t)(b * Hb + h) * Lb) + l) * DKb + dk] = o;
                }
                {
                    int m = m_lo + 8, b = m >> 11, l = m & 2047;
                    float2 o; o.x = acc[mt][nt][2] + bv2.x; o.y = acc[mt][nt][3] + bv2.y;
                    *(float2*)&Y[(((size_t)(b * Hb + h) * Lb) + l) * DKb + dk] = o;
                }
            }
        }
    }
}

// ---------------------------------------------------------------------------
// Kernel 2: approx M[bh,q] = max_k(Q.K) - mean_k(Q.K), single-pass tf32,
// cvt hoisted to tile-load time.  (FROZEN from R13)
// ---------------------------------------------------------------------------
__global__ void __launch_bounds__(256) mscore_tf32_kernel()
{
    extern __shared__ float smdyn[];
    float (*Qs)[68] = (float (*)[68])smdyn;
    float (*Ks)[68] = (float (*)[68])(smdyn + 128 * 68);
    float* rM = smdyn + 2 * 128 * 68;   // [2][128]
    float* rS = rM + 2 * 128;           // [2][128]

    int bh = blockIdx.y;
    int q0 = blockIdx.x * 128;
    int tid  = threadIdx.x;
    int lane = tid & 31, warp = tid >> 5;
    int wm = warp >> 1, wn = warp & 1;
    int gr = lane >> 2, gc = lane & 3;

    const float* Qg = g_Q + (size_t)bh * Lb * DKb;
    const float* Kg = g_K + (size_t)bh * Lb * DKb;

    int lr = tid >> 4, lc = (tid & 15) * 4;
    #pragma unroll
    for (int i = 0; i < 8; i++) {
        int r = lr + i * 16;
        float4 v = *(const float4*)&Qg[(size_t)(q0 + r) * DKb + lc];
        v.x = __uint_as_float(tf32_of(v.x));
        v.y = __uint_as_float(tf32_of(v.y));
        v.z = __uint_as_float(tf32_of(v.z));
        v.w = __uint_as_float(tf32_of(v.w));
        *(float4*)&Qs[r][lc] = v;
    }

    float rmax[2][2], rsum[2][2];
    #pragma unroll
    for (int a = 0; a < 2; a++)
        #pragma unroll
        for (int b = 0; b < 2; b++) { rmax[a][b] = -INFINITY; rsum[a][b] = 0.f; }

    float acc[2][8][4];
    #pragma unroll
    for (int mt = 0; mt < 2; mt++)
        #pragma unroll
        for (int nt = 0; nt < 8; nt++)
            #pragma unroll
            for (int r = 0; r < 4; r++) acc[mt][nt][r] = 0.f;

    for (int kt = 0; kt < Lb; kt += 128) {
        __syncthreads();
        #pragma unroll
        for (int i = 0; i < 8; i++) {
            int r = lr + i * 16;
            float4 v = *(const float4*)&Kg[(size_t)(kt + r) * DKb + lc];
            v.x = __uint_as_float(tf32_of(v.x));
            v.y = __uint_as_float(tf32_of(v.y));
            v.z = __uint_as_float(tf32_of(v.z));
            v.w = __uint_as_float(tf32_of(v.w));
            *(float4*)&Ks[r][lc] = v;
        }
        __syncthreads();

        #pragma unroll
        for (int k8 = 0; k8 < 64; k8 += 8) {
            uint32_t ah[2][4];
            #pragma unroll
            for (int mt = 0; mt < 2; mt++) {
                int rb = wm * 32 + mt * 16;
                ah[mt][0] = __float_as_uint(Qs[rb + gr][k8 + gc]);
                ah[mt][1] = __float_as_uint(Qs[rb + gr + 8][k8 + gc]);
                ah[mt][2] = __float_as_uint(Qs[rb + gr][k8 + gc + 4]);
                ah[mt][3] = __float_as_uint(Qs[rb + gr + 8][k8 + gc + 4]);
            }
            #pragma unroll
            for (int nt = 0; nt < 8; nt++) {
                int nb = wn * 64 + nt * 8;
                uint32_t bh0 = __float_as_uint(Ks[nb + gr][k8 + gc]);
                uint32_t bh1 = __float_as_uint(Ks[nb + gr][k8 + gc + 4]);
                #pragma unroll
                for (int mt = 0; mt < 2; mt++)
                    mma8(acc[mt][nt], ah[mt][0], ah[mt][1], ah[mt][2], ah[mt][3], bh0, bh1);
            }
        }

        #pragma unroll
        for (int mt = 0; mt < 2; mt++) {
            float mx0 = -INFINITY, mx1 = -INFINITY, s0 = 0.f, s1 = 0.f;
            #pragma unroll
            for (int nt = 0; nt < 8; nt++) {
                mx0 = fmaxf(mx0, fmaxf(acc[mt][nt][0], acc[mt][nt][1]));
                mx1 = fmaxf(mx1, fmaxf(acc[mt][nt][2], acc[mt][nt][3]));
                s0 += acc[mt][nt][0] + acc[mt][nt][1];
                s1 += acc[mt][nt][2] + acc[mt][nt][3];
                acc[mt][nt][0] = 0.f; acc[mt][nt][1] = 0.f;
                acc[mt][nt][2] = 0.f; acc[mt][nt][3] = 0.f;
            }
            rmax[mt][0] = fmaxf(rmax[mt][0], mx0);
            rmax[mt][1] = fmaxf(rmax[mt][1], mx1);
            rsum[mt][0] += s0;
            rsum[mt][1] += s1;
        }
    }

    #pragma unroll
    for (int mt = 0; mt < 2; mt++)
        #pragma unroll
        for (int hf = 0; hf < 2; hf++) {
            float m = rmax[mt][hf], s = rsum[mt][hf];
            #pragma unroll
            for (int o = 1; o < 4; o <<= 1) {
                m = fmaxf(m, __shfl_xor_sync(0xffffffffu, m, o));
                s += __shfl_xor_sync(0xffffffffu, s, o);
            }
            if (gc == 0) {
                int row = wm * 32 + mt * 16 + hf * 8 + gr;
                rM[wn * 128 + row] = m;
                rS[wn * 128 + row] = s;
            }
        }
    __syncthreads();
    if (tid < 128) {
        float m = fmaxf(rM[tid], rM[128 + tid]);
        float s = rS[tid] + rS[128 + tid];
        g_M[bh * Lb + q0 + tid] = m - s * (1.f / (float)Lb);
    }
}

// ---------------------------------------------------------------------------
// Kernel 3: candidate selection via MSB-first radix select, parallel
// suffix-scan boundary search (same threshold T and candidate set as R14).
// ---------------------------------------------------------------------------
__global__ void __launch_bounds__(256) cand_select_kernel()
{
    __shared__ unsigned int ukeys[Lb];      // 8 KB
    __shared__ unsigned int hist[256];
    __shared__ unsigned int suf[257];
    __shared__ unsigned int prefix_sh;
    __shared__ int remaining_sh;
    __shared__ int cntHigh, cntTie;

    int bh = blockIdx.x;
    int t  = threadIdx.x;

    // monotone map: ascending uint order == ascending float order
    for (int i = t; i < Lb; i += 256) {
        unsigned int u = __float_as_uint(g_M[bh * Lb + i]);
        ukeys[i] = (u & 0x80000000u) ? ~u : (u | 0x80000000u);
    }
    if (t == 0) { cntHigh = 0; cntTie = 0; suf[256] = 0; }
    __syncthreads();

    unsigned int prefix = 0;
    int K = CAND;                       // rank from the top within prefix group
    #pragma unroll
    for (int pass = 0; pass < 4; pass++) {
        int shift = 24 - pass * 8;
        hist[t] = 0;
        __syncthreads();
        unsigned int mask = (pass == 0) ? 0u : (0xFFFFFFFFu << (32 - 8 * pass));
        for (int i = t; i < Lb; i += 256) {
            unsigned int u = ukeys[i];
            if ((u & mask) == prefix)
                atomicAdd(&hist[(u >> shift) & 0xFF], 1u);
        }
        __syncthreads();
        // inclusive suffix sum: suf[t] = sum_{b >= t} hist[b]
        suf[t] = hist[t];
        __syncthreads();
        #pragma unroll
        for (int off = 1; off < 256; off <<= 1) {
            unsigned int v = (t + off < 256) ? suf[t + off] : 0u;
            __syncthreads();
            suf[t] += v;
            __syncthreads();
        }
        // boundary bin: suf[t] >= K and suf[t] - hist[t] < K  (unique t)
        unsigned int sg = suf[t] - hist[t];   // strictly-greater count
        if (suf[t] >= (unsigned int)K && sg < (unsigned int)K) {
            prefix_sh = prefix | ((unsigned int)t << shift);
            remaining_sh = K - (int)sg;
        }
        __syncthreads();
        prefix = prefix_sh;
        K = remaining_sh;
        __syncthreads();
    }

    unsigned int T = prefix;            // exact CAND-th largest key
    for (int i = t; i < Lb; i += 256) {
        if (ukeys[i] > T) {
            int p = atomicAdd(&cntHigh, 1);
            g_cand[bh * CAND + p] = i;
        }
    }
    __syncthreads();
    int base = cntHigh;                 // == CAND - K
    for (int i = t; i < Lb; i += 256) {
        if (ukeys[i] == T) {
            int p = atomicAdd(&cntTie, 1);
            if (base + p < CAND)
                g_cand[bh * CAND + base + p] = i;
        }
    }
}

// ---------------------------------------------------------------------------
// Kernel 4: exact fp32 refinement of M for the candidates.  (FROZEN)
// ---------------------------------------------------------------------------
__global__ void __launch_bounds__(CAND) refine_kernel()
{
    __shared__ float4 Ks[128][16];
    int bh = blockIdx.y;
    int s0 = blockIdx.x * 128;
    int t  = threadIdx.x;

    int qi = g_cand[bh * CAND + t];
    const float4* Qp = (const float4*)(g_Q + ((size_t)bh * Lb + qi) * DKb);
    float4 qr[16];
    #pragma unroll
    for (int j = 0; j < 16; j++) qr[j] = Qp[j];

    const float4* Kg = (const float4*)(g_K + ((size_t)bh * Lb + s0) * DKb);
    #pragma unroll
    for (int i = 0; i < 32; i++) {
        int lin = t + i * CAND;
        int r = lin >> 4, c = lin & 15;
        Ks[r][c] = Kg[r * 16 + c];
    }
    __syncthreads();

    float mx = -INFINITY, sm = 0.f;
    for (int k = 0; k < 128; k++) {
        float p0 = 0.f, p1 = 0.f, p2 = 0.f, p3 = 0.f;
        #pragma unroll
        for (int j = 0; j < 16; j++) {
            float4 kv = Ks[k][j];
            float4 qv = qr[j];
            p0 += qv.x * kv.x;
            p1 += qv.y * kv.y;
            p2 += qv.z * kv.z;
            p3 += qv.w * kv.w;
        }
        float s = (p0 + p1) + (p2 + p3);
        mx = fmaxf(mx, s);
        sm += s;
    }
    g_pM[(bh * RSPL + blockIdx.x) * CAND + t] = mx;
    g_pS[(bh * RSPL + blockIdx.x) * CAND + t] = sm;
}

// ---------------------------------------------------------------------------
// Kernel 5: combine refine partials -> exact M, final top-40.  (FROZEN)
// ---------------------------------------------------------------------------
__global__ void __launch_bounds__(CAND) finalsel_kernel()
{
    __shared__ float sv[CAND];
    __shared__ int   si[CAND];
    __shared__ float rv[CAND];
    __shared__ int   ri[CAND];

    int bh = blockIdx.x;
    int t  = threadIdx.x;

    float m = -INFINITY, s = 0.f;
    for (int sp = 0; sp < RSPL; sp++) {
        m = fmaxf(m, g_pM[(bh * RSPL + sp) * CAND + t]);
        s += g_pS[(bh * RSPL + sp) * CAND + t];
    }
    sv[t] = m - s * (1.f / (float)Lb);
    si[t] = g_cand[bh * CAND + t];
    __syncthreads();

    for (int u = 0; u < Ub; u++) {
        rv[t] = sv[t]; ri[t] = t;   // slot index for invalidation
        __syncthreads();
        for (int st = CAND / 2; st > 0; st >>= 1) {
            if (t < st) {
                float va = rv[t], vb = rv[t + st];
                int sa = ri[t], sb = ri[t + st];
                if (vb > va || (vb == va && si[sb] < si[sa])) {
                    rv[t] = vb; ri[t] = sb;
                }
            }
            __syncthreads();
        }
        if (t == 0) {
            g_top[bh * Ub + u] = si[ri[0]];
            sv[ri[0]] = -INFINITY;
        }
        __syncthreads();
    }
}

// ---------------------------------------------------------------------------
// Kernel 6: sparse attention (smem-tiled score dots).  (FROZEN from R14)
// ---------------------------------------------------------------------------
__global__ void __launch_bounds__(128) attn_kernel(float* __restrict__ out)
{
    __shared__ float s[Lb];             // 8 KB
    __shared__ float Kt[128][68];       // 34 KB
    __shared__ float redA[4];
    __shared__ float redB[4];
    __shared__ float accs[128];

    int u  = blockIdx.x;
    int bh = blockIdx.y;
    int b  = bh >> 4;
    int h  = bh & 15;
    int t = threadIdx.x, lane = t & 31, w = t >> 5;

    int q = g_top[bh * Ub + u];

    float4 qr[16];
    const float4* Qp = (const float4*)(g_Q + ((size_t)bh * Lb + q) * DKb);
    #pragma unroll
    for (int j = 0; j < 16; j++) qr[j] = Qp[j];

    const float4* Kg4 = (const float4*)(g_K + (size_t)bh * Lb * DKb);

    for (int kt = 0; kt < Lb; kt += 128) {
        __syncthreads();
        #pragma unroll
        for (int i = 0; i < 16; i++) {
            int lin = t + i * 128;
            int r = lin >> 4, c = lin & 15;
            *(float4*)&Kt[r][c * 4] = Kg4[(size_t)(kt + r) * 16 + c];
        }
        __syncthreads();

        int k = kt + t;
        float p0 = 0.f, p1 = 0.f, p2 = 0.f, p3 = 0.f;
        #pragma unroll
        for (int j = 0; j < 16; j++) {
            float4 kv = *(const float4*)&Kt[t][j * 4];
            float4 qv = qr[j];
            p0 += qv.x * kv.x;
            p1 += qv.y * kv.y;
            p2 += qv.z * kv.z;
            p3 += qv.w * kv.w;
        }
        float dot = (p0 + p1) + (p2 + p3);
        s[k] = dot * 0.125f + ((k > q) ? -1e9f : 0.f);
    }
    __syncthreads();

    float lm = -INFINITY;
    for (int k = t; k < Lb; k += 128) lm = fmaxf(lm, s[k]);
    #pragma unroll
    for (int o = 16; o; o >>= 1)
        lm = fmaxf(lm, __shfl_xor_sync(0xffffffffu, lm, o));
    if (lane == 0) redA[w] = lm;
    __syncthreads();
    float mv = fmaxf(fmaxf(redA[0], redA[1]), fmaxf(redA[2], redA[3]));

    float ls = 0.f;
    for (int k = t; k < Lb; k += 128) {
        float e = __expf(s[k] - mv);
        s[k] = e;
        ls += e;
    }
    #pragma unroll
    for (int o = 16; o; o >>= 1) ls += __shfl_xor_sync(0xffffffffu, ls, o);
    if (lane == 0) redB[w] = ls;
    __syncthreads();
    float inv = 1.f / (redB[0] + redB[1] + redB[2] + redB[3]);

    float* probs = out + (size_t)Bb * Ub * Db;
    size_t po = ((size_t)(bh * Ub + u)) * Lb;
    for (int k = t; k < Lb; k += 128) probs[po + k] = s[k] * inv;

    int dk = t & 63, half = t >> 6;
    const float* Vp = g_V + (size_t)bh * Lb * DKb + dk;
    int kbase = half * (Lb / 2);
    float a0 = 0.f, a1 = 0.f, a2 = 0.f, a3 = 0.f;
    for (int k = kbase; k < kbase + Lb / 2; k += 4) {
        a0 += s[k]     * Vp[(size_t)(k)     * DKb];
        a1 += s[k + 1] * Vp[(size_t)(k + 1) * DKb];
        a2 += s[k + 2] * Vp[(size_t)(k + 2) * DKb];
        a3 += s[k + 3] * Vp[(size_t)(k + 3) * DKb];
    }
    accs[t] = (a0 + a1) + (a2 + a3);
    __syncthreads();
    if (t < 64)
        out[((size_t)(b * Ub + u)) * Db + h * DKb + t] =
            (accs[t] + accs[t + 64]) * inv;
}

// ---------------------------------------------------------------------------
extern "C" void kernel_launch(void* const* d_in, const int* in_sizes, int n_in,
                              void* d_out, int out_size)
{
    const float* query = (const float*)d_in[0];
    const float* key   = (const float*)d_in[1];
    const float* value = (const float*)d_in[2];
    const float* Wq    = (const float*)d_in[3];
    const float* bq    = (const float*)d_in[4];
    const float* Wk    = (const float*)d_in[5];
    const float* bk    = (const float*)d_in[6];
    const float* Wv    = (const float*)d_in[7];
    const float* bv    = (const float*)d_in[8];
    float* out = (float*)d_out;

    const int mscoreSmem = (2 * 128 * 68 + 4 * 128) * 4;  // 71680 B
    cudaFuncSetAttribute(mscore_tf32_kernel,
                         cudaFuncAttributeMaxDynamicSharedMemorySize, mscoreSmem);

    dim3 glf(8, 32, 3);   // N/128, M/128, {Q, K, V}
    linear_fused_kernel<<<glf, 256>>>(query, Wq, bq, key, Wk, bk, value, Wv, bv);

    mscore_tf32_kernel<<<dim3(Lb / 128, BHb), 256, mscoreSmem>>>();
    cand_select_kernel<<<BHb, 256>>>();
    refine_kernel<<<dim3(RSPL, BHb), CAND>>>();
    finalsel_kernel<<<BHb, CAND>>>();
    attn_kernel<<<dim3(Ub, BHb), 128>>>(out);
}